// round 7
// baseline (speedup 1.0000x reference)
#include <cuda_runtime.h>
#include <cuda_bf16.h>
#include <math.h>
#include <cstdint>

#define NLAYER 6
#define DV     512
#define NH     8
#define HD     64
#define DFF    2048
#define BB     8
#define LL     1024
#define MM     (BB*LL)
#define QKV_STRIDE (3*DV)

// ---------------- scratch ----------------
__device__ float g_out [MM*DV];
__device__ float g_qkv [MM*3*DV];
__device__ float g_tmp [MM*DV];
__device__ unsigned char g_kpm[MM];

#define W_IN_SZ   (NLAYER*3*DV*DV)
#define W_OUT_SZ  (NLAYER*DV*DV)
#define W_L1_SZ   (NLAYER*DFF*DV)
#define W_L2_SZ   (NLAYER*DV*DFF)
#define W_TOT     (W_IN_SZ+W_OUT_SZ+W_L1_SZ+W_L2_SZ)
#define OFF_IN    0
#define OFF_OUT   (W_IN_SZ)
#define OFF_L1    (W_IN_SZ+W_OUT_SZ)
#define OFF_L2    (W_IN_SZ+W_OUT_SZ+W_L1_SZ)
__device__ __nv_bfloat16 g_whib[W_TOT];
__device__ __nv_bfloat16 g_wlob[W_TOT];
__device__ __nv_bfloat16 g_ahib[MM*DFF];   // d_model-wide activations (hi)
__device__ __nv_bfloat16 g_alob[MM*DFF];
__device__ __nv_bfloat16 g_hhib[MM*DFF];   // ffn hidden (hi)
__device__ __nv_bfloat16 g_hlob[MM*DFF];

// ---------------- packed f32x2 helpers ----------------
typedef unsigned long long u64t;
__device__ __forceinline__ u64t fma2(u64t a, u64t b, u64t c) {
    u64t d; asm("fma.rn.f32x2 %0, %1, %2, %3;" : "=l"(d) : "l"(a), "l"(b), "l"(c)); return d;
}
__device__ __forceinline__ u64t mul2(u64t a, u64t b) {
    u64t d; asm("mul.rn.f32x2 %0, %1, %2;" : "=l"(d) : "l"(a), "l"(b)); return d;
}
__device__ __forceinline__ u64t pack2(float lo, float hi) {
    u64t r; unsigned l = __float_as_uint(lo), h = __float_as_uint(hi);
    asm("mov.b64 %0, {%1, %2};" : "=l"(r) : "r"(l), "r"(h)); return r;
}
__device__ __forceinline__ u64t dup2(float x) { return pack2(x, x); }
__device__ __forceinline__ float2 unpk2(u64t v) {
    unsigned lo, hi; asm("mov.b64 {%0, %1}, %2;" : "=r"(lo), "=r"(hi) : "l"(v));
    return make_float2(__uint_as_float(lo), __uint_as_float(hi));
}

// ---------------- smem / mma helpers ----------------
__device__ __forceinline__ uint32_t s2u(const void* p) {
    uint32_t a;
    asm("{ .reg .u64 t; cvta.to.shared.u64 t, %1; cvt.u32.u64 %0, t; }" : "=r"(a) : "l"(p));
    return a;
}
__device__ __forceinline__ void cpa16(uint32_t dst, const void* src) {
    asm volatile("cp.async.cg.shared.global [%0], [%1], 16;" :: "r"(dst), "l"(src) : "memory");
}
__device__ __forceinline__ void cpa_commit() { asm volatile("cp.async.commit_group;" ::: "memory"); }
__device__ __forceinline__ void cpa_wait0() { asm volatile("cp.async.wait_group 0;" ::: "memory"); }
__device__ __forceinline__ void cpa_wait1() { asm volatile("cp.async.wait_group 1;" ::: "memory"); }
__device__ __forceinline__ void ldmx4(uint32_t* r, uint32_t addr) {
    asm volatile("ldmatrix.sync.aligned.m8n8.x4.shared.b16 {%0,%1,%2,%3}, [%4];"
        : "=r"(r[0]), "=r"(r[1]), "=r"(r[2]), "=r"(r[3]) : "r"(addr));
}
__device__ __forceinline__ void mma_bf16(float* d, const uint32_t* a, const uint32_t* b) {
    asm volatile("mma.sync.aligned.m16n8k16.row.col.f32.bf16.bf16.f32 "
        "{%0,%1,%2,%3}, {%4,%5,%6,%7}, {%8,%9}, {%0,%1,%2,%3};"
        : "+f"(d[0]), "+f"(d[1]), "+f"(d[2]), "+f"(d[3])
        : "r"(a[0]), "r"(a[1]), "r"(a[2]), "r"(a[3]), "r"(b[0]), "r"(b[1]));
}

// ---------------- key padding mask ----------------
__global__ void kpm_kernel(const float* __restrict__ x, unsigned char* __restrict__ kpm)
{
    int row = blockIdx.x;
    int t = threadIdx.x;
    int nz = 0;
    for (int c = t; c < DV; c += 128)
        nz |= (x[(size_t)row * DV + c] != 0.0f) ? 1 : 0;
    nz = __syncthreads_or(nz);
    if (t == 0) kpm[row] = nz ? 0 : 1;
}

// ---------------- copy + hi/lo split (initial x) ----------------
__global__ void copy_split_kernel(const float* __restrict__ src, float* __restrict__ dst,
                                  __nv_bfloat16* __restrict__ hi, __nv_bfloat16* __restrict__ lo, int n4)
{
    int i = blockIdx.x * blockDim.x + threadIdx.x;
    if (i >= n4) return;
    float4 v = ((const float4*)src)[i];
    ((float4*)dst)[i] = v;
    __nv_bfloat16 h0 = __float2bfloat16_rn(v.x), h1 = __float2bfloat16_rn(v.y);
    __nv_bfloat16 h2 = __float2bfloat16_rn(v.z), h3 = __float2bfloat16_rn(v.w);
    __nv_bfloat162* hp = (__nv_bfloat162*)hi;
    __nv_bfloat162* lp = (__nv_bfloat162*)lo;
    hp[2*i]   = __nv_bfloat162(h0, h1);
    hp[2*i+1] = __nv_bfloat162(h2, h3);
    lp[2*i]   = __nv_bfloat162(__float2bfloat16_rn(v.x - __bfloat162float(h0)),
                               __float2bfloat16_rn(v.y - __bfloat162float(h1)));
    lp[2*i+1] = __nv_bfloat162(__float2bfloat16_rn(v.z - __bfloat162float(h2)),
                               __float2bfloat16_rn(v.w - __bfloat162float(h3)));
}

// ---------------- weight hi/lo split ----------------
__global__ void splitb_kernel(const float* __restrict__ src,
                              __nv_bfloat16* __restrict__ hi,
                              __nv_bfloat16* __restrict__ lo, int n4)
{
    int i = blockIdx.x * blockDim.x + threadIdx.x;
    if (i >= n4) return;
    float4 v = ((const float4*)src)[i];
    __nv_bfloat16 h0 = __float2bfloat16_rn(v.x), h1 = __float2bfloat16_rn(v.y);
    __nv_bfloat16 h2 = __float2bfloat16_rn(v.z), h3 = __float2bfloat16_rn(v.w);
    __nv_bfloat162* hp = (__nv_bfloat162*)hi;
    __nv_bfloat162* lp = (__nv_bfloat162*)lo;
    hp[2*i]   = __nv_bfloat162(h0, h1);
    hp[2*i+1] = __nv_bfloat162(h2, h3);
    lp[2*i]   = __nv_bfloat162(__float2bfloat16_rn(v.x - __bfloat162float(h0)),
                               __float2bfloat16_rn(v.y - __bfloat162float(h1)));
    lp[2*i+1] = __nv_bfloat162(__float2bfloat16_rn(v.z - __bfloat162float(h2)),
                               __float2bfloat16_rn(v.w - __bfloat162float(h3)));
}

// ---------------- HMMA bf16 hi/lo GEMM ----------------
#define GSM_STAGE 32768
#define GSM_TOTAL (2*GSM_STAGE)

__device__ __forceinline__ uint32_t swz(int row, int kch) {
    return (uint32_t)(row * 64 + (((kch + ((row >> 1) & 3)) & 3) << 4));
}

template<bool GELU, bool SPLIT>
__global__ __launch_bounds__(256) void hmma_gemm(
    const __nv_bfloat16* __restrict__ Ahi, const __nv_bfloat16* __restrict__ Alo,
    const __nv_bfloat16* __restrict__ Whi, const __nv_bfloat16* __restrict__ Wlo,
    const float* __restrict__ bias, float* __restrict__ C,
    __nv_bfloat16* __restrict__ Chi, __nv_bfloat16* __restrict__ Clo,
    int N, int K)
{
    extern __shared__ __align__(16) char sm[];
    const uint32_t sb = s2u(sm);
    const int t = threadIdx.x;
    const int bm = blockIdx.y * 128, bn = blockIdx.x * 128;
    const int w = t >> 5, l = t & 31;
    const int wm = w & 3, wn = w >> 2;

    float acc[2][8][4];
#pragma unroll
    for (int mt = 0; mt < 2; mt++)
#pragma unroll
        for (int nt = 0; nt < 8; nt++)
#pragma unroll
            for (int e = 0; e < 4; e++) acc[mt][nt][e] = 0.0f;

    const int nch = K >> 5;

    auto load_stage = [&](int stage, int kt) {
        const uint32_t base = sb + stage * GSM_STAGE;
        const int k0 = kt << 5;
#pragma unroll
        for (int q = 0; q < 2; q++) {
            int ch = t + (q << 8);
            int row = ch >> 2, c = ch & 3;
            uint32_t so = swz(row, c);
            size_t ga = (size_t)(bm + row) * K + k0 + c * 8;
            size_t gb = (size_t)(bn + row) * K + k0 + c * 8;
            cpa16(base + so,          Ahi + ga);
            cpa16(base + 8192 + so,   Alo + ga);
            cpa16(base + 16384 + so,  Whi + gb);
            cpa16(base + 24576 + so,  Wlo + gb);
        }
        cpa_commit();
    };

    load_stage(0, 0);

    for (int c = 0; c < nch; ++c) {
        if (c + 1 < nch) { load_stage((c + 1) & 1, c + 1); cpa_wait1(); }
        else             { cpa_wait0(); }
        __syncthreads();

        const uint32_t base = sb + (c & 1) * GSM_STAGE;
#pragma unroll
        for (int kk = 0; kk < 2; kk++) {
            uint32_t ah[2][4], al[2][4];
#pragma unroll
            for (int mt = 0; mt < 2; mt++) {
                int row = wm * 32 + mt * 16 + (l & 15);
                int kch = kk * 2 + (l >> 4);
                uint32_t off = swz(row, kch);
                ldmx4(ah[mt], base + off);
                ldmx4(al[mt], base + 8192 + off);
            }
            uint32_t bh[8][2], bl[8][2];
#pragma unroll
            for (int nt2 = 0; nt2 < 4; nt2++) {
                int row = wn * 64 + nt2 * 16 + (l & 7) + ((l >> 4) << 3);
                int kch = kk * 2 + ((l >> 3) & 1);
                uint32_t off = swz(row, kch);
                uint32_t r[4];
                ldmx4(r, base + 16384 + off);
                bh[nt2*2][0] = r[0]; bh[nt2*2][1] = r[1];
                bh[nt2*2+1][0] = r[2]; bh[nt2*2+1][1] = r[3];
                ldmx4(r, base + 24576 + off);
                bl[nt2*2][0] = r[0]; bl[nt2*2][1] = r[1];
                bl[nt2*2+1][0] = r[2]; bl[nt2*2+1][1] = r[3];
            }
#pragma unroll
            for (int mt = 0; mt < 2; mt++)
#pragma unroll
                for (int nt = 0; nt < 8; nt++) {
                    mma_bf16(acc[mt][nt], ah[mt], bh[nt]);
                    mma_bf16(acc[mt][nt], ah[mt], bl[nt]);
                    mma_bf16(acc[mt][nt], al[mt], bh[nt]);
                }
        }
        __syncthreads();
    }

#pragma unroll
    for (int mt = 0; mt < 2; mt++) {
        int row = bm + wm * 32 + mt * 16 + (l >> 2);
#pragma unroll
        for (int nt = 0; nt < 8; nt++) {
            int col = bn + wn * 64 + nt * 8 + 2 * (l & 3);
            float b0 = bias[col], b1 = bias[col + 1];
            float v0 = acc[mt][nt][0] + b0;
            float v1 = acc[mt][nt][1] + b1;
            float v2 = acc[mt][nt][2] + b0;
            float v3 = acc[mt][nt][3] + b1;
            if (GELU) {
                v0 = 0.5f * v0 * (1.0f + erff(v0 * 0.70710678118654752f));
                v1 = 0.5f * v1 * (1.0f + erff(v1 * 0.70710678118654752f));
                v2 = 0.5f * v2 * (1.0f + erff(v2 * 0.70710678118654752f));
                v3 = 0.5f * v3 * (1.0f + erff(v3 * 0.70710678118654752f));
            }
            if (SPLIT) {
                __nv_bfloat16 h0 = __float2bfloat16_rn(v0), h1 = __float2bfloat16_rn(v1);
                __nv_bfloat16 h2 = __float2bfloat16_rn(v2), h3 = __float2bfloat16_rn(v3);
                *(__nv_bfloat162*)(Chi + (size_t)row * N + col) = __nv_bfloat162(h0, h1);
                *(__nv_bfloat162*)(Clo + (size_t)row * N + col) =
                    __nv_bfloat162(__float2bfloat16_rn(v0 - __bfloat162float(h0)),
                                   __float2bfloat16_rn(v1 - __bfloat162float(h1)));
                *(__nv_bfloat162*)(Chi + (size_t)(row + 8) * N + col) = __nv_bfloat162(h2, h3);
                *(__nv_bfloat162*)(Clo + (size_t)(row + 8) * N + col) =
                    __nv_bfloat162(__float2bfloat16_rn(v2 - __bfloat162float(h2)),
                                   __float2bfloat16_rn(v3 - __bfloat162float(h3)));
            } else {
                *(float2*)(C + (size_t)row * N + col)       = make_float2(v0, v1);
                *(float2*)(C + (size_t)(row + 8) * N + col) = make_float2(v2, v3);
            }
        }
    }
}

// ---------------- flash attention: 2 threads per query (split-d), bf16 hi/lo output ----------------
#define KT2 16
__global__ __launch_bounds__(256) void attn_kernel(
    const float* __restrict__ qkv, const float* __restrict__ dist_emb,
    const unsigned char* __restrict__ kpm,
    __nv_bfloat16* __restrict__ ohi, __nv_bfloat16* __restrict__ olo)
{
    __shared__ __align__(16) float sK[KT2][HD];
    __shared__ __align__(16) float sV[KT2][HD];
    __shared__ float sb[LL];
    __shared__ unsigned char skpm[LL];

    const int bh = blockIdx.x;
    const int b = bh / NH, h = bh % NH;
    const int qbase = blockIdx.y * 128;
    const int t = threadIdx.x;
    const int u = t >> 1;          // query slot 0..127
    const int half = t & 1;        // d-half
    const int i = qbase + u;

    for (int d = t; d < LL; d += 256) {
        sb[d] = dist_emb[d * NH + h];
        skpm[d] = kpm[b * LL + d];
    }

    // own 32 dims of q
    ulonglong2 qp[8];
    const ulonglong2* qg = (const ulonglong2*)(qkv + (size_t)(b * LL + i) * QKV_STRIDE + h * HD + half * 32);
#pragma unroll
    for (int n = 0; n < 8; n++) qp[n] = qg[n];

    float m = -1e30f, lsum = 0.0f;
    u64t accp[16];
#pragma unroll
    for (int n = 0; n < 16; n++) accp[n] = 0ULL;

    __syncthreads();

    const float scale = 0.125f;
    const int jend = qbase + 128;

    for (int jt = 0; jt < jend; jt += KT2) {
        {
            // 256 threads: each loads one float4 of K and one of V (16x64 each)
            int row = t >> 4;
            int kc  = (t & 15) * 4;
            const float* kp = qkv + (size_t)(b * LL + jt + row) * QKV_STRIDE + DV   + h * HD + kc;
            const float* vp = qkv + (size_t)(b * LL + jt + row) * QKV_STRIDE + 2*DV + h * HD + kc;
            *(float4*)&sK[row][kc] = *(const float4*)kp;
            *(float4*)&sV[row][kc] = *(const float4*)vp;
        }
        __syncthreads();

        float s[KT2];
#pragma unroll
        for (int jj = 0; jj < KT2; jj++) {
            int j = jt + jj;
            const ulonglong2* kr = (const ulonglong2*)&sK[jj][half * 32];
            u64t d2a = 0ULL, d2b = 0ULL;
#pragma unroll
            for (int n = 0; n < 8; n++) {
                ulonglong2 kk = kr[n];
                d2a = fma2(qp[n].x, kk.x, d2a);
                d2b = fma2(qp[n].y, kk.y, d2b);
            }
            float2 fa = unpk2(d2a), fb = unpk2(d2b);
            float dot_own = (fa.x + fa.y) + (fb.x + fb.y);
            float dotv = dot_own + __shfl_xor_sync(0xFFFFFFFFu, dot_own, 1);
            float sc = -1e30f;
            if (j <= i && !skpm[j]) sc = dotv * scale + sb[i - j];
            s[jj] = sc;
        }
        float tmax = s[0];
#pragma unroll
        for (int jj = 1; jj < KT2; jj++) tmax = fmaxf(tmax, s[jj]);
        float mnew = fmaxf(m, tmax);
        float alpha = (m > -1e29f) ? __expf(m - mnew) : 0.0f;
        lsum *= alpha;
        {
            u64t ad = dup2(alpha);
#pragma unroll
            for (int n = 0; n < 16; n++) accp[n] = mul2(accp[n], ad);
        }
        // exp work split by key parity across the lane pair
#pragma unroll
        for (int jj2 = 0; jj2 < KT2 / 2; jj2++) {
            int my_key = 2 * jj2 + half;
            float smy = s[my_key];
            float p_my = (smy > -1e29f) ? __expf(smy - mnew) : 0.0f;
            float p_oth = __shfl_xor_sync(0xFFFFFFFFu, p_my, 1);
            // p0 = key 2*jj2 (even), p1 = key 2*jj2+1 (odd), consistent on both lanes
            float p0 = half ? p_oth : p_my;
            float p1 = half ? p_my : p_oth;
            lsum += p0 + p1;
            u64t pd0 = dup2(p0), pd1 = dup2(p1);
            const ulonglong2* vr0 = (const ulonglong2*)&sV[2 * jj2][half * 32];
            const ulonglong2* vr1 = (const ulonglong2*)&sV[2 * jj2 + 1][half * 32];
#pragma unroll
            for (int n = 0; n < 8; n++) {
                ulonglong2 v0 = vr0[n];
                ulonglong2 v1 = vr1[n];
                accp[2*n]   = fma2(pd0, v0.x, accp[2*n]);
                accp[2*n+1] = fma2(pd0, v0.y, accp[2*n+1]);
                accp[2*n]   = fma2(pd1, v1.x, accp[2*n]);
                accp[2*n+1] = fma2(pd1, v1.y, accp[2*n+1]);
            }
        }
        m = mnew;
        __syncthreads();
    }

    float inv = 1.0f / lsum;
    size_t obase = (size_t)(b * LL + i) * DV + h * HD + half * 32;
#pragma unroll
    for (int n = 0; n < 8; n++) {
        float2 e = unpk2(accp[2*n]);
        float2 o = unpk2(accp[2*n+1]);
        float f0 = e.x * inv, f1 = e.y * inv, f2 = o.x * inv, f3 = o.y * inv;
        __nv_bfloat16 h0 = __float2bfloat16_rn(f0), h1 = __float2bfloat16_rn(f1);
        __nv_bfloat16 h2 = __float2bfloat16_rn(f2), h3 = __float2bfloat16_rn(f3);
        *(__nv_bfloat162*)(ohi + obase + 4*n)     = __nv_bfloat162(h0, h1);
        *(__nv_bfloat162*)(ohi + obase + 4*n + 2) = __nv_bfloat162(h2, h3);
        *(__nv_bfloat162*)(olo + obase + 4*n) =
            __nv_bfloat162(__float2bfloat16_rn(f0 - __bfloat162float(h0)),
                           __float2bfloat16_rn(f1 - __bfloat162float(h1)));
        *(__nv_bfloat162*)(olo + obase + 4*n + 2) =
            __nv_bfloat162(__float2bfloat16_rn(f2 - __bfloat162float(h2)),
                           __float2bfloat16_rn(f3 - __bfloat162float(h3)));
    }
}

// ---------------- residual + LayerNorm (+ optional bf16 hi/lo out) ----------------
__global__ __launch_bounds__(128) void ln_kernel(
    const float* __restrict__ x, const float* __restrict__ res,
    const float* __restrict__ g, const float* __restrict__ beta,
    float* __restrict__ outp,
    __nv_bfloat16* __restrict__ ohi, __nv_bfloat16* __restrict__ olo)
{
    const int row = blockIdx.x;
    const int t = threadIdx.x;
    const float* xr = x + (size_t)row * DV;

    float v[4];
#pragma unroll
    for (int k = 0; k < 4; k++) {
        int c = k * 128 + t;
        float val = xr[c];
        if (res) val += res[(size_t)row * DV + c];
        v[k] = val;
    }
    float s = 0.0f, ss = 0.0f;
#pragma unroll
    for (int k = 0; k < 4; k++) { s += v[k]; ss += v[k] * v[k]; }
#pragma unroll
    for (int o = 16; o > 0; o >>= 1) {
        s  += __shfl_xor_sync(0xFFFFFFFFu, s,  o);
        ss += __shfl_xor_sync(0xFFFFFFFFu, ss, o);
    }
    __shared__ float rs[4], rss[4];
    int w = t >> 5;
    if ((t & 31) == 0) { rs[w] = s; rss[w] = ss; }
    __syncthreads();
    s  = rs[0] + rs[1] + rs[2] + rs[3];
    ss = rss[0] + rss[1] + rss[2] + rss[3];
    float mean = s * (1.0f / DV);
    float var  = ss * (1.0f / DV) - mean * mean;
    float r = rsqrtf(var + 1e-5f);
#pragma unroll
    for (int k = 0; k < 4; k++) {
        int c = k * 128 + t;
        float val = (v[k] - mean) * r * g[c] + beta[c];
        outp[(size_t)row * DV + c] = val;
        if (ohi) {
            __nv_bfloat16 hh = __float2bfloat16_rn(val);
            ohi[(size_t)row * DV + c] = hh;
            olo[(size_t)row * DV + c] = __float2bfloat16_rn(val - __bfloat162float(hh));
        }
    }
}

// ---------------- host launcher ----------------
extern "C" void kernel_launch(void* const* d_in, const int* in_sizes, int n_in,
                              void* d_out, int out_size)
{
    (void)in_sizes; (void)n_in; (void)out_size;
    const float* x         = (const float*)d_in[0];
    const float* dist_emb  = (const float*)d_in[1];
    const float* in_proj_w = (const float*)d_in[2];
    const float* in_proj_b = (const float*)d_in[3];
    const float* out_w     = (const float*)d_in[4];
    const float* out_b     = (const float*)d_in[5];
    const float* lin1_w    = (const float*)d_in[6];
    const float* lin1_b    = (const float*)d_in[7];
    const float* lin2_w    = (const float*)d_in[8];
    const float* lin2_b    = (const float*)d_in[9];
    const float* ln1_g     = (const float*)d_in[10];
    const float* ln1_bp    = (const float*)d_in[11];
    const float* ln2_g     = (const float*)d_in[12];
    const float* ln2_bp    = (const float*)d_in[13];
    const float* lnf_g     = (const float*)d_in[14];
    const float* lnf_bp    = (const float*)d_in[15];

    float *p_out, *p_qkv, *p_tmp;
    __nv_bfloat16 *p_whi, *p_wlo, *p_ahi, *p_alo, *p_hhi, *p_hlo;
    unsigned char* p_kpm;
    cudaGetSymbolAddress((void**)&p_out,  g_out);
    cudaGetSymbolAddress((void**)&p_qkv,  g_qkv);
    cudaGetSymbolAddress((void**)&p_tmp,  g_tmp);
    cudaGetSymbolAddress((void**)&p_whi,  g_whib);
    cudaGetSymbolAddress((void**)&p_wlo,  g_wlob);
    cudaGetSymbolAddress((void**)&p_ahi,  g_ahib);
    cudaGetSymbolAddress((void**)&p_alo,  g_alob);
    cudaGetSymbolAddress((void**)&p_hhi,  g_hhib);
    cudaGetSymbolAddress((void**)&p_hlo,  g_hlob);
    cudaGetSymbolAddress((void**)&p_kpm,  g_kpm);

    cudaFuncSetAttribute(hmma_gemm<false,false>, cudaFuncAttributeMaxDynamicSharedMemorySize, GSM_TOTAL);
    cudaFuncSetAttribute(hmma_gemm<true,true>,   cudaFuncAttributeMaxDynamicSharedMemorySize, GSM_TOTAL);

    kpm_kernel<<<MM, 128>>>(x, p_kpm);
    {
        int n4 = MM * DV / 4;
        copy_split_kernel<<<(n4 + 255) / 256, 256>>>(x, p_out, p_ahi, p_alo, n4);
    }

    // split weights once
    {
        int n4;
        n4 = W_IN_SZ  / 4; splitb_kernel<<<(n4 + 255) / 256, 256>>>(in_proj_w, p_whi + OFF_IN,  p_wlo + OFF_IN,  n4);
        n4 = W_OUT_SZ / 4; splitb_kernel<<<(n4 + 255) / 256, 256>>>(out_w,     p_whi + OFF_OUT, p_wlo + OFF_OUT, n4);
        n4 = W_L1_SZ  / 4; splitb_kernel<<<(n4 + 255) / 256, 256>>>(lin1_w,    p_whi + OFF_L1,  p_wlo + OFF_L1,  n4);
        n4 = W_L2_SZ  / 4; splitb_kernel<<<(n4 + 255) / 256, 256>>>(lin2_w,    p_whi + OFF_L2,  p_wlo + OFF_L2,  n4);
    }

    for (int l = 0; l < NLAYER; l++) {
        const __nv_bfloat16* whi_in = p_whi + OFF_IN  + (size_t)l * 3 * DV * DV;
        const __nv_bfloat16* wlo_in = p_wlo + OFF_IN  + (size_t)l * 3 * DV * DV;
        const __nv_bfloat16* whi_o  = p_whi + OFF_OUT + (size_t)l * DV * DV;
        const __nv_bfloat16* wlo_o  = p_wlo + OFF_OUT + (size_t)l * DV * DV;
        const __nv_bfloat16* whi_1  = p_whi + OFF_L1  + (size_t)l * DFF * DV;
        const __nv_bfloat16* wlo_1  = p_wlo + OFF_L1  + (size_t)l * DFF * DV;
        const __nv_bfloat16* whi_2  = p_whi + OFF_L2  + (size_t)l * DV * DFF;
        const __nv_bfloat16* wlo_2  = p_wlo + OFF_L2  + (size_t)l * DV * DFF;
        const float* bq  = in_proj_b + (size_t)l * 3 * DV;
        const float* bo  = out_b     + (size_t)l * DV;
        const float* b1  = lin1_b    + (size_t)l * DFF;
        const float* b2  = lin2_b    + (size_t)l * DV;

        // QKV projection (A = ahi/alo from prev ln2 / init)
        hmma_gemm<false,false><<<dim3(3 * DV / 128, MM / 128), 256, GSM_TOTAL>>>(
            p_ahi, p_alo, whi_in, wlo_in, bq, p_qkv, nullptr, nullptr, 3 * DV, DV);
        // attention -> writes attn activation directly as hi/lo bf16
        attn_kernel<<<dim3(BB * NH, LL / 128), 256>>>(p_qkv, dist_emb, p_kpm, p_ahi, p_alo);
        // output projection
        hmma_gemm<false,false><<<dim3(DV / 128, MM / 128), 256, GSM_TOTAL>>>(
            p_ahi, p_alo, whi_o, wlo_o, bo, p_tmp, nullptr, nullptr, DV, DV);
        // residual + LN1 -> fp32 + hi/lo
        ln_kernel<<<MM, 128>>>(p_out, p_tmp, ln1_g + (size_t)l * DV, ln1_bp + (size_t)l * DV,
                               p_out, p_ahi, p_alo);
        // FFN up: gelu epilogue writes hi/lo directly
        hmma_gemm<true,true><<<dim3(DFF / 128, MM / 128), 256, GSM_TOTAL>>>(
            p_ahi, p_alo, whi_1, wlo_1, b1, nullptr, p_hhi, p_hlo, DFF, DV);
        // FFN down
        hmma_gemm<false,false><<<dim3(DV / 128, MM / 128), 256, GSM_TOTAL>>>(
            p_hhi, p_hlo, whi_2, wlo_2, b2, p_tmp, nullptr, nullptr, DV, DFF);
        // residual + LN2 -> fp32 + hi/lo (next layer's GEMM input)
        ln_kernel<<<MM, 128>>>(p_out, p_tmp, ln2_g + (size_t)l * DV, ln2_bp + (size_t)l * DV,
                               p_out, p_ahi, p_alo);
    }

    ln_kernel<<<MM, 128>>>(p_out, (const float*)nullptr, lnf_g, lnf_bp, (float*)d_out,
                           nullptr, nullptr);
}

// round 8
// speedup vs baseline: 1.2210x; 1.2210x over previous
#include <cuda_runtime.h>
#include <cuda_bf16.h>
#include <math.h>
#include <cstdint>

#define NLAYER 6
#define DV     512
#define NH     8
#define HD     64
#define DFF    2048
#define BB     8
#define LL     1024
#define MM     (BB*LL)
#define QKV_STRIDE (3*DV)

// ---------------- scratch ----------------
__device__ float g_out [MM*DV];
__device__ float g_qkv [MM*3*DV];
__device__ float g_tmp [MM*DV];
__device__ unsigned char g_kpm[MM];

#define W_IN_SZ   (NLAYER*3*DV*DV)
#define W_OUT_SZ  (NLAYER*DV*DV)
#define W_L1_SZ   (NLAYER*DFF*DV)
#define W_L2_SZ   (NLAYER*DV*DFF)
#define W_TOT     (W_IN_SZ+W_OUT_SZ+W_L1_SZ+W_L2_SZ)
#define OFF_IN    0
#define OFF_OUT   (W_IN_SZ)
#define OFF_L1    (W_IN_SZ+W_OUT_SZ)
#define OFF_L2    (W_IN_SZ+W_OUT_SZ+W_L1_SZ)
__device__ __nv_bfloat16 g_whib[W_TOT];
__device__ __nv_bfloat16 g_wlob[W_TOT];
__device__ __nv_bfloat16 g_ahib[MM*DFF];   // d_model-wide activations (hi)
__device__ __nv_bfloat16 g_alob[MM*DFF];
__device__ __nv_bfloat16 g_hhib[MM*DFF];   // ffn hidden (hi)
__device__ __nv_bfloat16 g_hlob[MM*DFF];

// ---------------- packed f32x2 helpers ----------------
typedef unsigned long long u64t;
__device__ __forceinline__ u64t fma2(u64t a, u64t b, u64t c) {
    u64t d; asm("fma.rn.f32x2 %0, %1, %2, %3;" : "=l"(d) : "l"(a), "l"(b), "l"(c)); return d;
}
__device__ __forceinline__ u64t mul2(u64t a, u64t b) {
    u64t d; asm("mul.rn.f32x2 %0, %1, %2;" : "=l"(d) : "l"(a), "l"(b)); return d;
}
__device__ __forceinline__ u64t pack2(float lo, float hi) {
    u64t r; unsigned l = __float_as_uint(lo), h = __float_as_uint(hi);
    asm("mov.b64 %0, {%1, %2};" : "=l"(r) : "r"(l), "r"(h)); return r;
}
__device__ __forceinline__ u64t dup2(float x) { return pack2(x, x); }
__device__ __forceinline__ float2 unpk2(u64t v) {
    unsigned lo, hi; asm("mov.b64 {%0, %1}, %2;" : "=r"(lo), "=r"(hi) : "l"(v));
    return make_float2(__uint_as_float(lo), __uint_as_float(hi));
}

// ---------------- smem / mma helpers ----------------
__device__ __forceinline__ uint32_t s2u(const void* p) {
    uint32_t a;
    asm("{ .reg .u64 t; cvta.to.shared.u64 t, %1; cvt.u32.u64 %0, t; }" : "=r"(a) : "l"(p));
    return a;
}
__device__ __forceinline__ void cpa16(uint32_t dst, const void* src) {
    asm volatile("cp.async.cg.shared.global [%0], [%1], 16;" :: "r"(dst), "l"(src) : "memory");
}
__device__ __forceinline__ void cpa_commit() { asm volatile("cp.async.commit_group;" ::: "memory"); }
__device__ __forceinline__ void cpa_wait0() { asm volatile("cp.async.wait_group 0;" ::: "memory"); }
__device__ __forceinline__ void cpa_wait1() { asm volatile("cp.async.wait_group 1;" ::: "memory"); }
__device__ __forceinline__ void ldmx4(uint32_t* r, uint32_t addr) {
    asm volatile("ldmatrix.sync.aligned.m8n8.x4.shared.b16 {%0,%1,%2,%3}, [%4];"
        : "=r"(r[0]), "=r"(r[1]), "=r"(r[2]), "=r"(r[3]) : "r"(addr));
}
__device__ __forceinline__ void mma_bf16(float* d, const uint32_t* a, const uint32_t* b) {
    asm volatile("mma.sync.aligned.m16n8k16.row.col.f32.bf16.bf16.f32 "
        "{%0,%1,%2,%3}, {%4,%5,%6,%7}, {%8,%9}, {%0,%1,%2,%3};"
        : "+f"(d[0]), "+f"(d[1]), "+f"(d[2]), "+f"(d[3])
        : "r"(a[0]), "r"(a[1]), "r"(a[2]), "r"(a[3]), "r"(b[0]), "r"(b[1]));
}

// ---------------- key padding mask ----------------
__global__ void kpm_kernel(const float* __restrict__ x, unsigned char* __restrict__ kpm)
{
    int row = blockIdx.x;
    int t = threadIdx.x;
    int nz = 0;
    for (int c = t; c < DV; c += 128)
        nz |= (x[(size_t)row * DV + c] != 0.0f) ? 1 : 0;
    nz = __syncthreads_or(nz);
    if (t == 0) kpm[row] = nz ? 0 : 1;
}

// ---------------- copy + hi/lo split (initial x) ----------------
__global__ void copy_split_kernel(const float* __restrict__ src, float* __restrict__ dst,
                                  __nv_bfloat16* __restrict__ hi, __nv_bfloat16* __restrict__ lo, int n4)
{
    int i = blockIdx.x * blockDim.x + threadIdx.x;
    if (i >= n4) return;
    float4 v = ((const float4*)src)[i];
    ((float4*)dst)[i] = v;
    __nv_bfloat16 h0 = __float2bfloat16_rn(v.x), h1 = __float2bfloat16_rn(v.y);
    __nv_bfloat16 h2 = __float2bfloat16_rn(v.z), h3 = __float2bfloat16_rn(v.w);
    __nv_bfloat162* hp = (__nv_bfloat162*)hi;
    __nv_bfloat162* lp = (__nv_bfloat162*)lo;
    hp[2*i]   = __nv_bfloat162(h0, h1);
    hp[2*i+1] = __nv_bfloat162(h2, h3);
    lp[2*i]   = __nv_bfloat162(__float2bfloat16_rn(v.x - __bfloat162float(h0)),
                               __float2bfloat16_rn(v.y - __bfloat162float(h1)));
    lp[2*i+1] = __nv_bfloat162(__float2bfloat16_rn(v.z - __bfloat162float(h2)),
                               __float2bfloat16_rn(v.w - __bfloat162float(h3)));
}

// ---------------- weight hi/lo split ----------------
__global__ void splitb_kernel(const float* __restrict__ src,
                              __nv_bfloat16* __restrict__ hi,
                              __nv_bfloat16* __restrict__ lo, int n4)
{
    int i = blockIdx.x * blockDim.x + threadIdx.x;
    if (i >= n4) return;
    float4 v = ((const float4*)src)[i];
    __nv_bfloat16 h0 = __float2bfloat16_rn(v.x), h1 = __float2bfloat16_rn(v.y);
    __nv_bfloat16 h2 = __float2bfloat16_rn(v.z), h3 = __float2bfloat16_rn(v.w);
    __nv_bfloat162* hp = (__nv_bfloat162*)hi;
    __nv_bfloat162* lp = (__nv_bfloat162*)lo;
    hp[2*i]   = __nv_bfloat162(h0, h1);
    hp[2*i+1] = __nv_bfloat162(h2, h3);
    lp[2*i]   = __nv_bfloat162(__float2bfloat16_rn(v.x - __bfloat162float(h0)),
                               __float2bfloat16_rn(v.y - __bfloat162float(h1)));
    lp[2*i+1] = __nv_bfloat162(__float2bfloat16_rn(v.z - __bfloat162float(h2)),
                               __float2bfloat16_rn(v.w - __bfloat162float(h3)));
}

// ---------------- HMMA bf16 hi/lo GEMM ----------------
#define GSM_STAGE 32768
#define GSM_TOTAL (2*GSM_STAGE)

__device__ __forceinline__ uint32_t swz(int row, int kch) {
    return (uint32_t)(row * 64 + (((kch + ((row >> 1) & 3)) & 3) << 4));
}

template<bool GELU, bool SPLIT>
__global__ __launch_bounds__(256) void hmma_gemm(
    const __nv_bfloat16* __restrict__ Ahi, const __nv_bfloat16* __restrict__ Alo,
    const __nv_bfloat16* __restrict__ Whi, const __nv_bfloat16* __restrict__ Wlo,
    const float* __restrict__ bias, float* __restrict__ C,
    __nv_bfloat16* __restrict__ Chi, __nv_bfloat16* __restrict__ Clo,
    int N, int K)
{
    extern __shared__ __align__(16) char sm[];
    const uint32_t sb = s2u(sm);
    const int t = threadIdx.x;
    const int bm = blockIdx.y * 128, bn = blockIdx.x * 128;
    const int w = t >> 5, l = t & 31;
    const int wm = w & 3, wn = w >> 2;

    float acc[2][8][4];
#pragma unroll
    for (int mt = 0; mt < 2; mt++)
#pragma unroll
        for (int nt = 0; nt < 8; nt++)
#pragma unroll
            for (int e = 0; e < 4; e++) acc[mt][nt][e] = 0.0f;

    const int nch = K >> 5;

    auto load_stage = [&](int stage, int kt) {
        const uint32_t base = sb + stage * GSM_STAGE;
        const int k0 = kt << 5;
#pragma unroll
        for (int q = 0; q < 2; q++) {
            int ch = t + (q << 8);
            int row = ch >> 2, c = ch & 3;
            uint32_t so = swz(row, c);
            size_t ga = (size_t)(bm + row) * K + k0 + c * 8;
            size_t gb = (size_t)(bn + row) * K + k0 + c * 8;
            cpa16(base + so,          Ahi + ga);
            cpa16(base + 8192 + so,   Alo + ga);
            cpa16(base + 16384 + so,  Whi + gb);
            cpa16(base + 24576 + so,  Wlo + gb);
        }
        cpa_commit();
    };

    load_stage(0, 0);

    for (int c = 0; c < nch; ++c) {
        if (c + 1 < nch) { load_stage((c + 1) & 1, c + 1); cpa_wait1(); }
        else             { cpa_wait0(); }
        __syncthreads();

        const uint32_t base = sb + (c & 1) * GSM_STAGE;
#pragma unroll
        for (int kk = 0; kk < 2; kk++) {
            uint32_t ah[2][4], al[2][4];
#pragma unroll
            for (int mt = 0; mt < 2; mt++) {
                int row = wm * 32 + mt * 16 + (l & 15);
                int kch = kk * 2 + (l >> 4);
                uint32_t off = swz(row, kch);
                ldmx4(ah[mt], base + off);
                ldmx4(al[mt], base + 8192 + off);
            }
            uint32_t bh[8][2], bl[8][2];
#pragma unroll
            for (int nt2 = 0; nt2 < 4; nt2++) {
                int row = wn * 64 + nt2 * 16 + (l & 7) + ((l >> 4) << 3);
                int kch = kk * 2 + ((l >> 3) & 1);
                uint32_t off = swz(row, kch);
                uint32_t r[4];
                ldmx4(r, base + 16384 + off);
                bh[nt2*2][0] = r[0]; bh[nt2*2][1] = r[1];
                bh[nt2*2+1][0] = r[2]; bh[nt2*2+1][1] = r[3];
                ldmx4(r, base + 24576 + off);
                bl[nt2*2][0] = r[0]; bl[nt2*2][1] = r[1];
                bl[nt2*2+1][0] = r[2]; bl[nt2*2+1][1] = r[3];
            }
#pragma unroll
            for (int mt = 0; mt < 2; mt++)
#pragma unroll
                for (int nt = 0; nt < 8; nt++) {
                    mma_bf16(acc[mt][nt], ah[mt], bh[nt]);
                    mma_bf16(acc[mt][nt], ah[mt], bl[nt]);
                    mma_bf16(acc[mt][nt], al[mt], bh[nt]);
                }
        }
        __syncthreads();
    }

#pragma unroll
    for (int mt = 0; mt < 2; mt++) {
        int row = bm + wm * 32 + mt * 16 + (l >> 2);
#pragma unroll
        for (int nt = 0; nt < 8; nt++) {
            int col = bn + wn * 64 + nt * 8 + 2 * (l & 3);
            float b0 = bias[col], b1 = bias[col + 1];
            float v0 = acc[mt][nt][0] + b0;
            float v1 = acc[mt][nt][1] + b1;
            float v2 = acc[mt][nt][2] + b0;
            float v3 = acc[mt][nt][3] + b1;
            if (GELU) {
                v0 = 0.5f * v0 * (1.0f + erff(v0 * 0.70710678118654752f));
                v1 = 0.5f * v1 * (1.0f + erff(v1 * 0.70710678118654752f));
                v2 = 0.5f * v2 * (1.0f + erff(v2 * 0.70710678118654752f));
                v3 = 0.5f * v3 * (1.0f + erff(v3 * 0.70710678118654752f));
            }
            if (SPLIT) {
                __nv_bfloat16 h0 = __float2bfloat16_rn(v0), h1 = __float2bfloat16_rn(v1);
                __nv_bfloat16 h2 = __float2bfloat16_rn(v2), h3 = __float2bfloat16_rn(v3);
                *(__nv_bfloat162*)(Chi + (size_t)row * N + col) = __nv_bfloat162(h0, h1);
                *(__nv_bfloat162*)(Clo + (size_t)row * N + col) =
                    __nv_bfloat162(__float2bfloat16_rn(v0 - __bfloat162float(h0)),
                                   __float2bfloat16_rn(v1 - __bfloat162float(h1)));
                *(__nv_bfloat162*)(Chi + (size_t)(row + 8) * N + col) = __nv_bfloat162(h2, h3);
                *(__nv_bfloat162*)(Clo + (size_t)(row + 8) * N + col) =
                    __nv_bfloat162(__float2bfloat16_rn(v2 - __bfloat162float(h2)),
                                   __float2bfloat16_rn(v3 - __bfloat162float(h3)));
            } else {
                *(float2*)(C + (size_t)row * N + col)       = make_float2(v0, v1);
                *(float2*)(C + (size_t)(row + 8) * N + col) = make_float2(v2, v3);
            }
        }
    }
}

// ---------------- flash attention (R6 layout: 1 thread/query) + bf16 hi/lo output ----------------
#define KT 8
__global__ __launch_bounds__(128) void attn_kernel(
    const float* __restrict__ qkv, const float* __restrict__ dist_emb,
    const unsigned char* __restrict__ kpm,
    __nv_bfloat16* __restrict__ ohi, __nv_bfloat16* __restrict__ olo)
{
    __shared__ __align__(16) float sK[KT][HD];
    __shared__ __align__(16) float sV[KT][HD];
    __shared__ float sb[LL];
    __shared__ unsigned char skpm[LL];

    const int bh = blockIdx.x;
    const int b = bh / NH, h = bh % NH;
    const int qbase = blockIdx.y * 128;
    const int t = threadIdx.x;
    const int i = qbase + t;

    for (int d = t; d < LL; d += 128) {
        sb[d] = dist_emb[d * NH + h];
        skpm[d] = kpm[b * LL + d];
    }

    ulonglong2 qp[16];
    const ulonglong2* qg = (const ulonglong2*)(qkv + (size_t)(b * LL + i) * QKV_STRIDE + h * HD);
#pragma unroll
    for (int n = 0; n < 16; n++) qp[n] = qg[n];

    float m = -1e30f, lsum = 0.0f;
    u64t accp[32];
#pragma unroll
    for (int n = 0; n < 32; n++) accp[n] = 0ULL;

    __syncthreads();

    const float scale = 0.125f;
    const int jend = qbase + 128;

    for (int jt = 0; jt < jend; jt += KT) {
        {
            int krow = t >> 4;
            int kc   = (t & 15) * 4;
            const float* kp = qkv + (size_t)(b * LL + jt + krow) * QKV_STRIDE + DV   + h * HD + kc;
            const float* vp = qkv + (size_t)(b * LL + jt + krow) * QKV_STRIDE + 2*DV + h * HD + kc;
            *(float4*)&sK[krow][kc] = *(const float4*)kp;
            *(float4*)&sV[krow][kc] = *(const float4*)vp;
        }
        __syncthreads();

        float s[KT];
#pragma unroll
        for (int jj = 0; jj < KT; jj++) {
            int j = jt + jj;
            const ulonglong2* kr = (const ulonglong2*)&sK[jj][0];
            u64t d2a = 0ULL, d2b = 0ULL;
#pragma unroll
            for (int n = 0; n < 16; n++) {
                ulonglong2 kk = kr[n];
                d2a = fma2(qp[n].x, kk.x, d2a);
                d2b = fma2(qp[n].y, kk.y, d2b);
            }
            float2 fa = unpk2(d2a), fb = unpk2(d2b);
            float dotv = (fa.x + fa.y) + (fb.x + fb.y);
            float sc = -1e30f;
            if (j <= i && !skpm[j]) sc = dotv * scale + sb[i - j];
            s[jj] = sc;
        }
        float tmax = s[0];
#pragma unroll
        for (int jj = 1; jj < KT; jj++) tmax = fmaxf(tmax, s[jj]);
        float mnew = fmaxf(m, tmax);
        float alpha = (m > -1e29f) ? __expf(m - mnew) : 0.0f;
        lsum *= alpha;
        {
            u64t ad = dup2(alpha);
#pragma unroll
            for (int n = 0; n < 32; n++) accp[n] = mul2(accp[n], ad);
        }
#pragma unroll
        for (int jj = 0; jj < KT; jj++) {
            float p = (s[jj] > -1e29f) ? __expf(s[jj] - mnew) : 0.0f;
            lsum += p;
            u64t pd = dup2(p);
            const ulonglong2* vr = (const ulonglong2*)&sV[jj][0];
#pragma unroll
            for (int n = 0; n < 16; n++) {
                ulonglong2 vv = vr[n];
                accp[2*n]   = fma2(pd, vv.x, accp[2*n]);
                accp[2*n+1] = fma2(pd, vv.y, accp[2*n+1]);
            }
        }
        m = mnew;
        __syncthreads();
    }

    float inv = 1.0f / lsum;
    size_t obase = (size_t)(b * LL + i) * DV + h * HD;
#pragma unroll
    for (int n = 0; n < 16; n++) {
        float2 e = unpk2(accp[2*n]);
        float2 o = unpk2(accp[2*n+1]);
        float f0 = e.x * inv, f1 = e.y * inv, f2 = o.x * inv, f3 = o.y * inv;
        __nv_bfloat16 h0 = __float2bfloat16_rn(f0), h1 = __float2bfloat16_rn(f1);
        __nv_bfloat16 h2 = __float2bfloat16_rn(f2), h3 = __float2bfloat16_rn(f3);
        *(__nv_bfloat162*)(ohi + obase + 4*n)     = __nv_bfloat162(h0, h1);
        *(__nv_bfloat162*)(ohi + obase + 4*n + 2) = __nv_bfloat162(h2, h3);
        *(__nv_bfloat162*)(olo + obase + 4*n) =
            __nv_bfloat162(__float2bfloat16_rn(f0 - __bfloat162float(h0)),
                           __float2bfloat16_rn(f1 - __bfloat162float(h1)));
        *(__nv_bfloat162*)(olo + obase + 4*n + 2) =
            __nv_bfloat162(__float2bfloat16_rn(f2 - __bfloat162float(h2)),
                           __float2bfloat16_rn(f3 - __bfloat162float(h3)));
    }
}

// ---------------- residual + LayerNorm (+ optional bf16 hi/lo out) ----------------
__global__ __launch_bounds__(128) void ln_kernel(
    const float* __restrict__ x, const float* __restrict__ res,
    const float* __restrict__ g, const float* __restrict__ beta,
    float* __restrict__ outp,
    __nv_bfloat16* __restrict__ ohi, __nv_bfloat16* __restrict__ olo)
{
    const int row = blockIdx.x;
    const int t = threadIdx.x;
    const float* xr = x + (size_t)row * DV;

    float v[4];
#pragma unroll
    for (int k = 0; k < 4; k++) {
        int c = k * 128 + t;
        float val = xr[c];
        if (res) val += res[(size_t)row * DV + c];
        v[k] = val;
    }
    float s = 0.0f, ss = 0.0f;
#pragma unroll
    for (int k = 0; k < 4; k++) { s += v[k]; ss += v[k] * v[k]; }
#pragma unroll
    for (int o = 16; o > 0; o >>= 1) {
        s  += __shfl_xor_sync(0xFFFFFFFFu, s,  o);
        ss += __shfl_xor_sync(0xFFFFFFFFu, ss, o);
    }
    __shared__ float rs[4], rss[4];
    int w = t >> 5;
    if ((t & 31) == 0) { rs[w] = s; rss[w] = ss; }
    __syncthreads();
    s  = rs[0] + rs[1] + rs[2] + rs[3];
    ss = rss[0] + rss[1] + rss[2] + rss[3];
    float mean = s * (1.0f / DV);
    float var  = ss * (1.0f / DV) - mean * mean;
    float r = rsqrtf(var + 1e-5f);
#pragma unroll
    for (int k = 0; k < 4; k++) {
        int c = k * 128 + t;
        float val = (v[k] - mean) * r * g[c] + beta[c];
        outp[(size_t)row * DV + c] = val;
        if (ohi) {
            __nv_bfloat16 hh = __float2bfloat16_rn(val);
            ohi[(size_t)row * DV + c] = hh;
            olo[(size_t)row * DV + c] = __float2bfloat16_rn(val - __bfloat162float(hh));
        }
    }
}

// ---------------- host launcher ----------------
extern "C" void kernel_launch(void* const* d_in, const int* in_sizes, int n_in,
                              void* d_out, int out_size)
{
    (void)in_sizes; (void)n_in; (void)out_size;
    const float* x         = (const float*)d_in[0];
    const float* dist_emb  = (const float*)d_in[1];
    const float* in_proj_w = (const float*)d_in[2];
    const float* in_proj_b = (const float*)d_in[3];
    const float* out_w     = (const float*)d_in[4];
    const float* out_b     = (const float*)d_in[5];
    const float* lin1_w    = (const float*)d_in[6];
    const float* lin1_b    = (const float*)d_in[7];
    const float* lin2_w    = (const float*)d_in[8];
    const float* lin2_b    = (const float*)d_in[9];
    const float* ln1_g     = (const float*)d_in[10];
    const float* ln1_bp    = (const float*)d_in[11];
    const float* ln2_g     = (const float*)d_in[12];
    const float* ln2_bp    = (const float*)d_in[13];
    const float* lnf_g     = (const float*)d_in[14];
    const float* lnf_bp    = (const float*)d_in[15];

    float *p_out, *p_qkv, *p_tmp;
    __nv_bfloat16 *p_whi, *p_wlo, *p_ahi, *p_alo, *p_hhi, *p_hlo;
    unsigned char* p_kpm;
    cudaGetSymbolAddress((void**)&p_out,  g_out);
    cudaGetSymbolAddress((void**)&p_qkv,  g_qkv);
    cudaGetSymbolAddress((void**)&p_tmp,  g_tmp);
    cudaGetSymbolAddress((void**)&p_whi,  g_whib);
    cudaGetSymbolAddress((void**)&p_wlo,  g_wlob);
    cudaGetSymbolAddress((void**)&p_ahi,  g_ahib);
    cudaGetSymbolAddress((void**)&p_alo,  g_alob);
    cudaGetSymbolAddress((void**)&p_hhi,  g_hhib);
    cudaGetSymbolAddress((void**)&p_hlo,  g_hlob);
    cudaGetSymbolAddress((void**)&p_kpm,  g_kpm);

    cudaFuncSetAttribute(hmma_gemm<false,false>, cudaFuncAttributeMaxDynamicSharedMemorySize, GSM_TOTAL);
    cudaFuncSetAttribute(hmma_gemm<true,true>,   cudaFuncAttributeMaxDynamicSharedMemorySize, GSM_TOTAL);

    kpm_kernel<<<MM, 128>>>(x, p_kpm);
    {
        int n4 = MM * DV / 4;
        copy_split_kernel<<<(n4 + 255) / 256, 256>>>(x, p_out, p_ahi, p_alo, n4);
    }

    // split weights once
    {
        int n4;
        n4 = W_IN_SZ  / 4; splitb_kernel<<<(n4 + 255) / 256, 256>>>(in_proj_w, p_whi + OFF_IN,  p_wlo + OFF_IN,  n4);
        n4 = W_OUT_SZ / 4; splitb_kernel<<<(n4 + 255) / 256, 256>>>(out_w,     p_whi + OFF_OUT, p_wlo + OFF_OUT, n4);
        n4 = W_L1_SZ  / 4; splitb_kernel<<<(n4 + 255) / 256, 256>>>(lin1_w,    p_whi + OFF_L1,  p_wlo + OFF_L1,  n4);
        n4 = W_L2_SZ  / 4; splitb_kernel<<<(n4 + 255) / 256, 256>>>(lin2_w,    p_whi + OFF_L2,  p_wlo + OFF_L2,  n4);
    }

    for (int l = 0; l < NLAYER; l++) {
        const __nv_bfloat16* whi_in = p_whi + OFF_IN  + (size_t)l * 3 * DV * DV;
        const __nv_bfloat16* wlo_in = p_wlo + OFF_IN  + (size_t)l * 3 * DV * DV;
        const __nv_bfloat16* whi_o  = p_whi + OFF_OUT + (size_t)l * DV * DV;
        const __nv_bfloat16* wlo_o  = p_wlo + OFF_OUT + (size_t)l * DV * DV;
        const __nv_bfloat16* whi_1  = p_whi + OFF_L1  + (size_t)l * DFF * DV;
        const __nv_bfloat16* wlo_1  = p_wlo + OFF_L1  + (size_t)l * DFF * DV;
        const __nv_bfloat16* whi_2  = p_whi + OFF_L2  + (size_t)l * DV * DFF;
        const __nv_bfloat16* wlo_2  = p_wlo + OFF_L2  + (size_t)l * DV * DFF;
        const float* bq  = in_proj_b + (size_t)l * 3 * DV;
        const float* bo  = out_b     + (size_t)l * DV;
        const float* b1  = lin1_b    + (size_t)l * DFF;
        const float* b2  = lin2_b    + (size_t)l * DV;

        // QKV projection (A = ahi/alo from prev ln2 / init)
        hmma_gemm<false,false><<<dim3(3 * DV / 128, MM / 128), 256, GSM_TOTAL>>>(
            p_ahi, p_alo, whi_in, wlo_in, bq, p_qkv, nullptr, nullptr, 3 * DV, DV);
        // attention -> writes attn activation directly as hi/lo bf16
        attn_kernel<<<dim3(BB * NH, LL / 128), 128>>>(p_qkv, dist_emb, p_kpm, p_ahi, p_alo);
        // output projection
        hmma_gemm<false,false><<<dim3(DV / 128, MM / 128), 256, GSM_TOTAL>>>(
            p_ahi, p_alo, whi_o, wlo_o, bo, p_tmp, nullptr, nullptr, DV, DV);
        // residual + LN1 -> fp32 + hi/lo
        ln_kernel<<<MM, 128>>>(p_out, p_tmp, ln1_g + (size_t)l * DV, ln1_bp + (size_t)l * DV,
                               p_out, p_ahi, p_alo);
        // FFN up: gelu epilogue writes hi/lo directly
        hmma_gemm<true,true><<<dim3(DFF / 128, MM / 128), 256, GSM_TOTAL>>>(
            p_ahi, p_alo, whi_1, wlo_1, b1, nullptr, p_hhi, p_hlo, DFF, DV);
        // FFN down
        hmma_gemm<false,false><<<dim3(DV / 128, MM / 128), 256, GSM_TOTAL>>>(
            p_hhi, p_hlo, whi_2, wlo_2, b2, p_tmp, nullptr, nullptr, DV, DFF);
        // residual + LN2 -> fp32 + hi/lo (next layer's GEMM input)
        ln_kernel<<<MM, 128>>>(p_out, p_tmp, ln2_g + (size_t)l * DV, ln2_bp + (size_t)l * DV,
                               p_out, p_ahi, p_alo);
    }

    ln_kernel<<<MM, 128>>>(p_out, (const float*)nullptr, lnf_g, lnf_bp, (float*)d_out,
                           nullptr, nullptr);
}

// round 10
// speedup vs baseline: 2.2564x; 1.8480x over previous
#include <cuda_runtime.h>
#include <cuda_bf16.h>
#include <math.h>
#include <cstdint>

#define NLAYER 6
#define DV     512
#define NH     8
#define HD     64
#define DFF    2048
#define BB     8
#define LL     1024
#define MM     (BB*LL)
#define QKV_STRIDE (3*DV)

// ---------------- scratch ----------------
__device__ float g_out [MM*DV];
__device__ float g_tmp [MM*DV];
__device__ unsigned char g_kpm[MM];

#define W_IN_SZ   (NLAYER*3*DV*DV)
#define W_OUT_SZ  (NLAYER*DV*DV)
#define W_L1_SZ   (NLAYER*DFF*DV)
#define W_L2_SZ   (NLAYER*DV*DFF)
#define W_TOT     (W_IN_SZ+W_OUT_SZ+W_L1_SZ+W_L2_SZ)
#define OFF_IN    0
#define OFF_OUT   (W_IN_SZ)
#define OFF_L1    (W_IN_SZ+W_OUT_SZ)
#define OFF_L2    (W_IN_SZ+W_OUT_SZ+W_L1_SZ)
__device__ __nv_bfloat16 g_whib[W_TOT];
__device__ __nv_bfloat16 g_wlob[W_TOT];
__device__ __nv_bfloat16 g_ahib[MM*DFF];
__device__ __nv_bfloat16 g_alob[MM*DFF];
__device__ __nv_bfloat16 g_hhib[MM*DFF];
__device__ __nv_bfloat16 g_hlob[MM*DFF];
__device__ __nv_bfloat16 g_qkvh[MM*3*DV];
__device__ __nv_bfloat16 g_qkvl[MM*3*DV];

// ---------------- smem / mma helpers ----------------
__device__ __forceinline__ uint32_t s2u(const void* p) {
    uint32_t a;
    asm("{ .reg .u64 t; cvta.to.shared.u64 t, %1; cvt.u32.u64 %0, t; }" : "=r"(a) : "l"(p));
    return a;
}
__device__ __forceinline__ void cpa16(uint32_t dst, const void* src) {
    asm volatile("cp.async.cg.shared.global [%0], [%1], 16;" :: "r"(dst), "l"(src) : "memory");
}
__device__ __forceinline__ void cpa_commit() { asm volatile("cp.async.commit_group;" ::: "memory"); }
__device__ __forceinline__ void cpa_wait0() { asm volatile("cp.async.wait_group 0;" ::: "memory"); }
__device__ __forceinline__ void cpa_wait1() { asm volatile("cp.async.wait_group 1;" ::: "memory"); }
__device__ __forceinline__ void ldmx4(uint32_t* r, uint32_t addr) {
    asm volatile("ldmatrix.sync.aligned.m8n8.x4.shared.b16 {%0,%1,%2,%3}, [%4];"
        : "=r"(r[0]), "=r"(r[1]), "=r"(r[2]), "=r"(r[3]) : "r"(addr));
}
__device__ __forceinline__ void ldmx4t(uint32_t* r, uint32_t addr) {
    asm volatile("ldmatrix.sync.aligned.m8n8.x4.trans.shared.b16 {%0,%1,%2,%3}, [%4];"
        : "=r"(r[0]), "=r"(r[1]), "=r"(r[2]), "=r"(r[3]) : "r"(addr));
}
__device__ __forceinline__ void mma_bf16(float* d, const uint32_t* a, const uint32_t* b) {
    asm volatile("mma.sync.aligned.m16n8k16.row.col.f32.bf16.bf16.f32 "
        "{%0,%1,%2,%3}, {%4,%5,%6,%7}, {%8,%9}, {%0,%1,%2,%3};"
        : "+f"(d[0]), "+f"(d[1]), "+f"(d[2]), "+f"(d[3])
        : "r"(a[0]), "r"(a[1]), "r"(a[2]), "r"(a[3]), "r"(b[0]), "r"(b[1]));
}

// hi/lo bf16x2 pair from two floats (x0 -> low half)
#define CVTPAIR(dsthi, dstlo, x0, x1) do { \
    uint32_t _hp; asm("cvt.rn.bf16x2.f32 %0, %1, %2;" : "=r"(_hp) : "f"(x1), "f"(x0)); \
    float _h0 = __uint_as_float(_hp << 16); \
    float _h1 = __uint_as_float(_hp & 0xFFFF0000u); \
    uint32_t _lp; asm("cvt.rn.bf16x2.f32 %0, %1, %2;" : "=r"(_lp) : "f"((x1) - _h1), "f"((x0) - _h0)); \
    (dsthi) = _hp; (dstlo) = _lp; } while(0)

// ---------------- key padding mask ----------------
__global__ void kpm_kernel(const float* __restrict__ x, unsigned char* __restrict__ kpm)
{
    int row = blockIdx.x;
    int t = threadIdx.x;
    int nz = 0;
    for (int c = t; c < DV; c += 128)
        nz |= (x[(size_t)row * DV + c] != 0.0f) ? 1 : 0;
    nz = __syncthreads_or(nz);
    if (t == 0) kpm[row] = nz ? 0 : 1;
}

// ---------------- copy + hi/lo split (initial x) ----------------
__global__ void copy_split_kernel(const float* __restrict__ src, float* __restrict__ dst,
                                  __nv_bfloat16* __restrict__ hi, __nv_bfloat16* __restrict__ lo, int n4)
{
    int i = blockIdx.x * blockDim.x + threadIdx.x;
    if (i >= n4) return;
    float4 v = ((const float4*)src)[i];
    ((float4*)dst)[i] = v;
    __nv_bfloat16 h0 = __float2bfloat16_rn(v.x), h1 = __float2bfloat16_rn(v.y);
    __nv_bfloat16 h2 = __float2bfloat16_rn(v.z), h3 = __float2bfloat16_rn(v.w);
    __nv_bfloat162* hp = (__nv_bfloat162*)hi;
    __nv_bfloat162* lp = (__nv_bfloat162*)lo;
    hp[2*i]   = __nv_bfloat162(h0, h1);
    hp[2*i+1] = __nv_bfloat162(h2, h3);
    lp[2*i]   = __nv_bfloat162(__float2bfloat16_rn(v.x - __bfloat162float(h0)),
                               __float2bfloat16_rn(v.y - __bfloat162float(h1)));
    lp[2*i+1] = __nv_bfloat162(__float2bfloat16_rn(v.z - __bfloat162float(h2)),
                               __float2bfloat16_rn(v.w - __bfloat162float(h3)));
}

// ---------------- weight hi/lo split ----------------
__global__ void splitb_kernel(const float* __restrict__ src,
                              __nv_bfloat16* __restrict__ hi,
                              __nv_bfloat16* __restrict__ lo, int n4)
{
    int i = blockIdx.x * blockDim.x + threadIdx.x;
    if (i >= n4) return;
    float4 v = ((const float4*)src)[i];
    __nv_bfloat16 h0 = __float2bfloat16_rn(v.x), h1 = __float2bfloat16_rn(v.y);
    __nv_bfloat16 h2 = __float2bfloat16_rn(v.z), h3 = __float2bfloat16_rn(v.w);
    __nv_bfloat162* hp = (__nv_bfloat162*)hi;
    __nv_bfloat162* lp = (__nv_bfloat162*)lo;
    hp[2*i]   = __nv_bfloat162(h0, h1);
    hp[2*i+1] = __nv_bfloat162(h2, h3);
    lp[2*i]   = __nv_bfloat162(__float2bfloat16_rn(v.x - __bfloat162float(h0)),
                               __float2bfloat16_rn(v.y - __bfloat162float(h1)));
    lp[2*i+1] = __nv_bfloat162(__float2bfloat16_rn(v.z - __bfloat162float(h2)),
                               __float2bfloat16_rn(v.w - __bfloat162float(h3)));
}

// ---------------- HMMA bf16 hi/lo GEMM ----------------
#define GSM_STAGE 32768
#define GSM_TOTAL (2*GSM_STAGE)

__device__ __forceinline__ uint32_t swz(int row, int kch) {
    return (uint32_t)(row * 64 + (((kch + ((row >> 1) & 3)) & 3) << 4));
}

template<bool GELU, bool SPLIT>
__global__ __launch_bounds__(256) void hmma_gemm(
    const __nv_bfloat16* __restrict__ Ahi, const __nv_bfloat16* __restrict__ Alo,
    const __nv_bfloat16* __restrict__ Whi, const __nv_bfloat16* __restrict__ Wlo,
    const float* __restrict__ bias, float* __restrict__ C,
    __nv_bfloat16* __restrict__ Chi, __nv_bfloat16* __restrict__ Clo,
    int N, int K)
{
    extern __shared__ __align__(16) char sm[];
    const uint32_t sb = s2u(sm);
    const int t = threadIdx.x;
    const int bm = blockIdx.y * 128, bn = blockIdx.x * 128;
    const int w = t >> 5, l = t & 31;
    const int wm = w & 3, wn = w >> 2;

    float acc[2][8][4];
#pragma unroll
    for (int mt = 0; mt < 2; mt++)
#pragma unroll
        for (int nt = 0; nt < 8; nt++)
#pragma unroll
            for (int e = 0; e < 4; e++) acc[mt][nt][e] = 0.0f;

    const int nch = K >> 5;

    auto load_stage = [&](int stage, int kt) {
        const uint32_t base = sb + stage * GSM_STAGE;
        const int k0 = kt << 5;
#pragma unroll
        for (int q = 0; q < 2; q++) {
            int ch = t + (q << 8);
            int row = ch >> 2, c = ch & 3;
            uint32_t so = swz(row, c);
            size_t ga = (size_t)(bm + row) * K + k0 + c * 8;
            size_t gb = (size_t)(bn + row) * K + k0 + c * 8;
            cpa16(base + so,          Ahi + ga);
            cpa16(base + 8192 + so,   Alo + ga);
            cpa16(base + 16384 + so,  Whi + gb);
            cpa16(base + 24576 + so,  Wlo + gb);
        }
        cpa_commit();
    };

    load_stage(0, 0);

    for (int c = 0; c < nch; ++c) {
        if (c + 1 < nch) { load_stage((c + 1) & 1, c + 1); cpa_wait1(); }
        else             { cpa_wait0(); }
        __syncthreads();

        const uint32_t base = sb + (c & 1) * GSM_STAGE;
#pragma unroll
        for (int kk = 0; kk < 2; kk++) {
            uint32_t ah[2][4], al[2][4];
#pragma unroll
            for (int mt = 0; mt < 2; mt++) {
                int row = wm * 32 + mt * 16 + (l & 15);
                int kch = kk * 2 + (l >> 4);
                uint32_t off = swz(row, kch);
                ldmx4(ah[mt], base + off);
                ldmx4(al[mt], base + 8192 + off);
            }
            uint32_t bh[8][2], bl[8][2];
#pragma unroll
            for (int nt2 = 0; nt2 < 4; nt2++) {
                int row = wn * 64 + nt2 * 16 + (l & 7) + ((l >> 4) << 3);
                int kch = kk * 2 + ((l >> 3) & 1);
                uint32_t off = swz(row, kch);
                uint32_t r[4];
                ldmx4(r, base + 16384 + off);
                bh[nt2*2][0] = r[0]; bh[nt2*2][1] = r[1];
                bh[nt2*2+1][0] = r[2]; bh[nt2*2+1][1] = r[3];
                ldmx4(r, base + 24576 + off);
                bl[nt2*2][0] = r[0]; bl[nt2*2][1] = r[1];
                bl[nt2*2+1][0] = r[2]; bl[nt2*2+1][1] = r[3];
            }
#pragma unroll
            for (int mt = 0; mt < 2; mt++)
#pragma unroll
                for (int nt = 0; nt < 8; nt++) {
                    mma_bf16(acc[mt][nt], ah[mt], bh[nt]);
                    mma_bf16(acc[mt][nt], ah[mt], bl[nt]);
                    mma_bf16(acc[mt][nt], al[mt], bh[nt]);
                }
        }
        __syncthreads();
    }

#pragma unroll
    for (int mt = 0; mt < 2; mt++) {
        int row = bm + wm * 32 + mt * 16 + (l >> 2);
#pragma unroll
        for (int nt = 0; nt < 8; nt++) {
            int col = bn + wn * 64 + nt * 8 + 2 * (l & 3);
            float b0 = bias[col], b1 = bias[col + 1];
            float v0 = acc[mt][nt][0] + b0;
            float v1 = acc[mt][nt][1] + b1;
            float v2 = acc[mt][nt][2] + b0;
            float v3 = acc[mt][nt][3] + b1;
            if (GELU) {
                v0 = 0.5f * v0 * (1.0f + erff(v0 * 0.70710678118654752f));
                v1 = 0.5f * v1 * (1.0f + erff(v1 * 0.70710678118654752f));
                v2 = 0.5f * v2 * (1.0f + erff(v2 * 0.70710678118654752f));
                v3 = 0.5f * v3 * (1.0f + erff(v3 * 0.70710678118654752f));
            }
            if (SPLIT) {
                uint32_t hp, lp;
                CVTPAIR(hp, lp, v0, v1);
                *(uint32_t*)(Chi + (size_t)row * N + col) = hp;
                *(uint32_t*)(Clo + (size_t)row * N + col) = lp;
                CVTPAIR(hp, lp, v2, v3);
                *(uint32_t*)(Chi + (size_t)(row + 8) * N + col) = hp;
                *(uint32_t*)(Clo + (size_t)(row + 8) * N + col) = lp;
            } else {
                *(float2*)(C + (size_t)row * N + col)       = make_float2(v0, v1);
                *(float2*)(C + (size_t)(row + 8) * N + col) = make_float2(v2, v3);
            }
        }
    }
}

// ---------------- mma.sync flash attention ----------------
// 256 thr / 8 warps; warp w owns 16 queries; block = 128 queries of one (b,h).
// K/V tiles: 64 keys, bf16 hi/lo, double-buffered cp.async.
// smem: stages 0/1 at 0/32768 (each: Kh 0, Kl 8192, Vh 16384, Vl 24576; rows 128B,
// chunk swizzle ch^(row&7)); sbias @65536 (4KB), smask @69632 (4KB). Q staged in stage0.
#define ASM_TOTAL 73728

__global__ __launch_bounds__(256, 1) void attn_mma(
    const __nv_bfloat16* __restrict__ qkvh, const __nv_bfloat16* __restrict__ qkvl,
    const float* __restrict__ dist_emb, const unsigned char* __restrict__ kpm,
    __nv_bfloat16* __restrict__ ohi, __nv_bfloat16* __restrict__ olo)
{
    extern __shared__ __align__(16) char sm[];
    const uint32_t sb0 = s2u(sm);
    const int bh = blockIdx.x;
    const int b = bh >> 3, h = bh & 7;
    const int qbi = (int)gridDim.y - 1 - (int)blockIdx.y;   // long blocks first
    const int qbase = qbi * 128;
    const int t = threadIdx.x;
    const int w = t >> 5, l = t & 31;

    float* sbias = (float*)(sm + 65536);
    float* smask = (float*)(sm + 69632);
    for (int d = t; d < LL; d += 256) {
        sbias[d] = dist_emb[d * NH + h];
        smask[d] = kpm[b * LL + d] ? -2e30f : 0.0f;
    }

    // stage Q (hi @ sb0, lo @ sb0+16384): 128 rows x 64 dims bf16, 128B rows
#pragma unroll
    for (int q = 0; q < 4; q++) {
        int c = t + q * 256;
        int row = c >> 3, ch = c & 7;
        size_t g = (size_t)(b * LL + qbase + row) * QKV_STRIDE + h * HD + ch * 8;
        uint32_t off = (uint32_t)(row * 128 + ((ch ^ (row & 7)) << 4));
        cpa16(sb0 + off, qkvh + g);
        cpa16(sb0 + 16384 + off, qkvl + g);
    }
    cpa_commit();
    cpa_wait0();
    __syncthreads();

    uint32_t qh[4][4], ql[4][4];
    {
        int qrow = w * 16 + (l & 15);
#pragma unroll
        for (int j = 0; j < 4; j++) {
            int ch = 2 * j + (l >> 4);
            uint32_t addr = sb0 + qrow * 128 + ((ch ^ (qrow & 7)) << 4);
            ldmx4(qh[j], addr);
            ldmx4(ql[j], addr + 16384);
        }
    }
    __syncthreads();   // done with Q staging region before K/V overwrite

    float o[8][4];
#pragma unroll
    for (int dt = 0; dt < 8; dt++)
#pragma unroll
        for (int e = 0; e < 4; e++) o[dt][e] = 0.0f;
    float m0 = -1e30f, m1 = -1e30f, ls0 = 0.0f, ls1 = 0.0f;
    const int i0 = qbase + w * 16 + (l >> 2);
    const int i1 = i0 + 8;
    const int ntile = (qbase + 128) >> 6;

    auto load_kv = [&](int stage, int jt) {
        const uint32_t base = sb0 + stage * 32768;
#pragma unroll
        for (int q = 0; q < 2; q++) {
            int c = t + q * 256;
            int row = c >> 3, ch = c & 7;
            size_t gk = (size_t)(b * LL + jt + row) * QKV_STRIDE + DV + h * HD + ch * 8;
            size_t gv = gk + DV;
            uint32_t off = (uint32_t)(row * 128 + ((ch ^ (row & 7)) << 4));
            cpa16(base + off,          qkvh + gk);
            cpa16(base + 8192 + off,   qkvl + gk);
            cpa16(base + 16384 + off,  qkvh + gv);
            cpa16(base + 24576 + off,  qkvl + gv);
        }
        cpa_commit();
    };

    load_kv(0, 0);

    for (int ti = 0; ti < ntile; ti++) {
        if (ti + 1 < ntile) { load_kv((ti + 1) & 1, (ti + 1) << 6); cpa_wait1(); }
        else                { cpa_wait0(); }
        __syncthreads();

        const int jt = ti << 6;
        if (jt <= qbase + w * 16 + 15) {
            const uint32_t kb = sb0 + (ti & 1) * 32768;

            // ---- S = Q K^T (3-term hi/lo) ----
            float s[8][4];
#pragma unroll
            for (int nt = 0; nt < 8; nt++)
#pragma unroll
                for (int e = 0; e < 4; e++) s[nt][e] = 0.0f;

            const int krow = (l & 7) + ((l >> 4) << 3);
#pragma unroll
            for (int kc = 0; kc < 4; kc++) {
                const int kch = 2 * kc + ((l >> 3) & 1);
#pragma unroll
                for (int nt2 = 0; nt2 < 4; nt2++) {
                    int row = nt2 * 16 + krow;
                    uint32_t addr = kb + row * 128 + ((kch ^ (row & 7)) << 4);
                    uint32_t rh[4], rl[4];
                    ldmx4(rh, addr);
                    ldmx4(rl, addr + 8192);
                    uint32_t b0h[2] = {rh[0], rh[1]}, b1h[2] = {rh[2], rh[3]};
                    uint32_t b0l[2] = {rl[0], rl[1]}, b1l[2] = {rl[2], rl[3]};
                    mma_bf16(s[nt2*2],   qh[kc], b0h);
                    mma_bf16(s[nt2*2],   qh[kc], b0l);
                    mma_bf16(s[nt2*2],   ql[kc], b0h);
                    mma_bf16(s[nt2*2+1], qh[kc], b1h);
                    mma_bf16(s[nt2*2+1], qh[kc], b1l);
                    mma_bf16(s[nt2*2+1], ql[kc], b1h);
                }
            }

            // ---- scale + bias + causal/kpm mask ----
            const float scale = 0.125f;
            const int jc = jt + 2 * (l & 3);
#pragma unroll
            for (int nt = 0; nt < 8; nt++) {
                int j0 = jc + nt * 8;
                float mk0 = smask[j0], mk1 = smask[j0 + 1];
                int d0 = i0 - j0;
                int d1 = i1 - j0;
                s[nt][0] = (d0 >= 0)     ? fmaf(s[nt][0], scale, sbias[d0]     + mk0) : -1e30f;
                s[nt][1] = (d0 >= 1)     ? fmaf(s[nt][1], scale, sbias[d0 - 1] + mk1) : -1e30f;
                s[nt][2] = (d1 >= 0)     ? fmaf(s[nt][2], scale, sbias[d1]     + mk0) : -1e30f;
                s[nt][3] = (d1 >= 1)     ? fmaf(s[nt][3], scale, sbias[d1 - 1] + mk1) : -1e30f;
            }

            // ---- online softmax ----
            float mx0 = -1e30f, mx1 = -1e30f;
#pragma unroll
            for (int nt = 0; nt < 8; nt++) {
                mx0 = fmaxf(mx0, fmaxf(s[nt][0], s[nt][1]));
                mx1 = fmaxf(mx1, fmaxf(s[nt][2], s[nt][3]));
            }
            mx0 = fmaxf(mx0, __shfl_xor_sync(0xFFFFFFFFu, mx0, 1));
            mx0 = fmaxf(mx0, __shfl_xor_sync(0xFFFFFFFFu, mx0, 2));
            mx1 = fmaxf(mx1, __shfl_xor_sync(0xFFFFFFFFu, mx1, 1));
            mx1 = fmaxf(mx1, __shfl_xor_sync(0xFFFFFFFFu, mx1, 2));
            float mn0 = fmaxf(m0, mx0), mn1 = fmaxf(m1, mx1);
            float a0 = __expf(m0 - mn0), a1 = __expf(m1 - mn1);
            m0 = mn0; m1 = mn1;
            ls0 *= a0; ls1 *= a1;
#pragma unroll
            for (int dt = 0; dt < 8; dt++) {
                o[dt][0] *= a0; o[dt][1] *= a0;
                o[dt][2] *= a1; o[dt][3] *= a1;
            }
#pragma unroll
            for (int nt = 0; nt < 8; nt++) {
                s[nt][0] = __expf(s[nt][0] - mn0);
                s[nt][1] = __expf(s[nt][1] - mn0);
                s[nt][2] = __expf(s[nt][2] - mn1);
                s[nt][3] = __expf(s[nt][3] - mn1);
                ls0 += s[nt][0] + s[nt][1];
                ls1 += s[nt][2] + s[nt][3];
            }

            // ---- P -> bf16 hi/lo A-fragments ----
            uint32_t ph[4][4], pl[4][4];
#pragma unroll
            for (int j = 0; j < 4; j++) {
                CVTPAIR(ph[j][0], pl[j][0], s[2*j][0],   s[2*j][1]);
                CVTPAIR(ph[j][1], pl[j][1], s[2*j][2],   s[2*j][3]);
                CVTPAIR(ph[j][2], pl[j][2], s[2*j+1][0], s[2*j+1][1]);
                CVTPAIR(ph[j][3], pl[j][3], s[2*j+1][2], s[2*j+1][3]);
            }

            // ---- O += P V (3-term) ----
            const int vsub = (l & 7) + (((l >> 3) & 1) << 3);
#pragma unroll
            for (int j = 0; j < 4; j++) {
                int vrow = j * 16 + vsub;
#pragma unroll
                for (int dp = 0; dp < 4; dp++) {
                    int ch = 2 * dp + (l >> 4);
                    uint32_t addr = kb + 16384 + vrow * 128 + ((ch ^ (vrow & 7)) << 4);
                    uint32_t rh[4], rl[4];
                    ldmx4t(rh, addr);
                    ldmx4t(rl, addr + 8192);
                    uint32_t v0h[2] = {rh[0], rh[1]}, v1h[2] = {rh[2], rh[3]};
                    uint32_t v0l[2] = {rl[0], rl[1]}, v1l[2] = {rl[2], rl[3]};
                    mma_bf16(o[2*dp],   ph[j], v0h);
                    mma_bf16(o[2*dp],   pl[j], v0h);
                    mma_bf16(o[2*dp],   ph[j], v0l);
                    mma_bf16(o[2*dp+1], ph[j], v1h);
                    mma_bf16(o[2*dp+1], pl[j], v1h);
                    mma_bf16(o[2*dp+1], ph[j], v1l);
                }
            }
        }
        __syncthreads();
    }

    // ---- finalize ----
    ls0 += __shfl_xor_sync(0xFFFFFFFFu, ls0, 1);
    ls0 += __shfl_xor_sync(0xFFFFFFFFu, ls0, 2);
    ls1 += __shfl_xor_sync(0xFFFFFFFFu, ls1, 1);
    ls1 += __shfl_xor_sync(0xFFFFFFFFu, ls1, 2);
    float inv0 = 1.0f / ls0, inv1 = 1.0f / ls1;

#pragma unroll
    for (int dt = 0; dt < 8; dt++) {
        int col = h * HD + dt * 8 + 2 * (l & 3);
        size_t r0 = (size_t)(b * LL + i0) * DV + col;
        size_t r1 = (size_t)(b * LL + i1) * DV + col;
        uint32_t hp, lp;
        CVTPAIR(hp, lp, o[dt][0] * inv0, o[dt][1] * inv0);
        *(uint32_t*)(ohi + r0) = hp;
        *(uint32_t*)(olo + r0) = lp;
        CVTPAIR(hp, lp, o[dt][2] * inv1, o[dt][3] * inv1);
        *(uint32_t*)(ohi + r1) = hp;
        *(uint32_t*)(olo + r1) = lp;
    }
}

// ---------------- residual + LayerNorm (+ optional bf16 hi/lo out) ----------------
__global__ __launch_bounds__(128) void ln_kernel(
    const float* __restrict__ x, const float* __restrict__ res,
    const float* __restrict__ g, const float* __restrict__ beta,
    float* __restrict__ outp,
    __nv_bfloat16* __restrict__ ohi, __nv_bfloat16* __restrict__ olo)
{
    const int row = blockIdx.x;
    const int t = threadIdx.x;
    const float* xr = x + (size_t)row * DV;

    float v[4];
#pragma unroll
    for (int k = 0; k < 4; k++) {
        int c = k * 128 + t;
        float val = xr[c];
        if (res) val += res[(size_t)row * DV + c];
        v[k] = val;
    }
    float s = 0.0f, ss = 0.0f;
#pragma unroll
    for (int k = 0; k < 4; k++) { s += v[k]; ss += v[k] * v[k]; }
#pragma unroll
    for (int o = 16; o > 0; o >>= 1) {
        s  += __shfl_xor_sync(0xFFFFFFFFu, s,  o);
        ss += __shfl_xor_sync(0xFFFFFFFFu, ss, o);
    }
    __shared__ float rs[4], rss[4];
    int w = t >> 5;
    if ((t & 31) == 0) { rs[w] = s; rss[w] = ss; }
    __syncthreads();
    s  = rs[0] + rs[1] + rs[2] + rs[3];
    ss = rss[0] + rss[1] + rss[2] + rss[3];
    float mean = s * (1.0f / DV);
    float var  = ss * (1.0f / DV) - mean * mean;
    float r = rsqrtf(var + 1e-5f);
#pragma unroll
    for (int k = 0; k < 4; k++) {
        int c = k * 128 + t;
        float val = (v[k] - mean) * r * g[c] + beta[c];
        outp[(size_t)row * DV + c] = val;
        if (ohi) {
            __nv_bfloat16 hh = __float2bfloat16_rn(val);
            ohi[(size_t)row * DV + c] = hh;
            olo[(size_t)row * DV + c] = __float2bfloat16_rn(val - __bfloat162float(hh));
        }
    }
}

// ---------------- host launcher ----------------
extern "C" void kernel_launch(void* const* d_in, const int* in_sizes, int n_in,
                              void* d_out, int out_size)
{
    (void)in_sizes; (void)n_in; (void)out_size;
    const float* x         = (const float*)d_in[0];
    const float* dist_emb  = (const float*)d_in[1];
    const float* in_proj_w = (const float*)d_in[2];
    const float* in_proj_b = (const float*)d_in[3];
    const float* out_w     = (const float*)d_in[4];
    const float* out_b     = (const float*)d_in[5];
    const float* lin1_w    = (const float*)d_in[6];
    const float* lin1_b    = (const float*)d_in[7];
    const float* lin2_w    = (const float*)d_in[8];
    const float* lin2_b    = (const float*)d_in[9];
    const float* ln1_g     = (const float*)d_in[10];
    const float* ln1_bp    = (const float*)d_in[11];
    const float* ln2_g     = (const float*)d_in[12];
    const float* ln2_bp    = (const float*)d_in[13];
    const float* lnf_g     = (const float*)d_in[14];
    const float* lnf_bp    = (const float*)d_in[15];

    float *p_out, *p_tmp;
    __nv_bfloat16 *p_whi, *p_wlo, *p_ahi, *p_alo, *p_hhi, *p_hlo, *p_qkvh, *p_qkvl;
    unsigned char* p_kpm;
    cudaGetSymbolAddress((void**)&p_out,  g_out);
    cudaGetSymbolAddress((void**)&p_tmp,  g_tmp);
    cudaGetSymbolAddress((void**)&p_whi,  g_whib);
    cudaGetSymbolAddress((void**)&p_wlo,  g_wlob);
    cudaGetSymbolAddress((void**)&p_ahi,  g_ahib);
    cudaGetSymbolAddress((void**)&p_alo,  g_alob);
    cudaGetSymbolAddress((void**)&p_hhi,  g_hhib);
    cudaGetSymbolAddress((void**)&p_hlo,  g_hlob);
    cudaGetSymbolAddress((void**)&p_qkvh, g_qkvh);
    cudaGetSymbolAddress((void**)&p_qkvl, g_qkvl);
    cudaGetSymbolAddress((void**)&p_kpm,  g_kpm);

    cudaFuncSetAttribute(hmma_gemm<false,false>, cudaFuncAttributeMaxDynamicSharedMemorySize, GSM_TOTAL);
    cudaFuncSetAttribute(hmma_gemm<false,true>,  cudaFuncAttributeMaxDynamicSharedMemorySize, GSM_TOTAL);
    cudaFuncSetAttribute(hmma_gemm<true,true>,   cudaFuncAttributeMaxDynamicSharedMemorySize, GSM_TOTAL);
    cudaFuncSetAttribute(attn_mma, cudaFuncAttributeMaxDynamicSharedMemorySize, ASM_TOTAL);

    kpm_kernel<<<MM, 128>>>(x, p_kpm);
    {
        int n4 = MM * DV / 4;
        copy_split_kernel<<<(n4 + 255) / 256, 256>>>(x, p_out, p_ahi, p_alo, n4);
    }

    // split weights once
    {
        int n4;
        n4 = W_IN_SZ  / 4; splitb_kernel<<<(n4 + 255) / 256, 256>>>(in_proj_w, p_whi + OFF_IN,  p_wlo + OFF_IN,  n4);
        n4 = W_OUT_SZ / 4; splitb_kernel<<<(n4 + 255) / 256, 256>>>(out_w,     p_whi + OFF_OUT, p_wlo + OFF_OUT, n4);
        n4 = W_L1_SZ  / 4; splitb_kernel<<<(n4 + 255) / 256, 256>>>(lin1_w,    p_whi + OFF_L1,  p_wlo + OFF_L1,  n4);
        n4 = W_L2_SZ  / 4; splitb_kernel<<<(n4 + 255) / 256, 256>>>(lin2_w,    p_whi + OFF_L2,  p_wlo + OFF_L2,  n4);
    }

    for (int l = 0; l < NLAYER; l++) {
        const __nv_bfloat16* whi_in = p_whi + OFF_IN  + (size_t)l * 3 * DV * DV;
        const __nv_bfloat16* wlo_in = p_wlo + OFF_IN  + (size_t)l * 3 * DV * DV;
        const __nv_bfloat16* whi_o  = p_whi + OFF_OUT + (size_t)l * DV * DV;
        const __nv_bfloat16* wlo_o  = p_wlo + OFF_OUT + (size_t)l * DV * DV;
        const __nv_bfloat16* whi_1  = p_whi + OFF_L1  + (size_t)l * DFF * DV;
        const __nv_bfloat16* wlo_1  = p_wlo + OFF_L1  + (size_t)l * DFF * DV;
        const __nv_bfloat16* whi_2  = p_whi + OFF_L2  + (size_t)l * DV * DFF;
        const __nv_bfloat16* wlo_2  = p_wlo + OFF_L2  + (size_t)l * DV * DFF;
        const float* bq  = in_proj_b + (size_t)l * 3 * DV;
        const float* bo  = out_b     + (size_t)l * DV;
        const float* b1  = lin1_b    + (size_t)l * DFF;
        const float* b2  = lin2_b    + (size_t)l * DV;

        // QKV projection -> bf16 hi/lo qkv
        hmma_gemm<false,true><<<dim3(3 * DV / 128, MM / 128), 256, GSM_TOTAL>>>(
            p_ahi, p_alo, whi_in, wlo_in, bq, nullptr, p_qkvh, p_qkvl, 3 * DV, DV);
        // mma flash attention -> attn activation as hi/lo bf16
        attn_mma<<<dim3(BB * NH, LL / 128), 256, ASM_TOTAL>>>(
            p_qkvh, p_qkvl, dist_emb, p_kpm, p_ahi, p_alo);
        // output projection
        hmma_gemm<false,false><<<dim3(DV / 128, MM / 128), 256, GSM_TOTAL>>>(
            p_ahi, p_alo, whi_o, wlo_o, bo, p_tmp, nullptr, nullptr, DV, DV);
        // residual + LN1 -> fp32 + hi/lo
        ln_kernel<<<MM, 128>>>(p_out, p_tmp, ln1_g + (size_t)l * DV, ln1_bp + (size_t)l * DV,
                               p_out, p_ahi, p_alo);
        // FFN up: gelu epilogue writes hi/lo directly
        hmma_gemm<true,true><<<dim3(DFF / 128, MM / 128), 256, GSM_TOTAL>>>(
            p_ahi, p_alo, whi_1, wlo_1, b1, nullptr, p_hhi, p_hlo, DFF, DV);
        // FFN down
        hmma_gemm<false,false><<<dim3(DV / 128, MM / 128), 256, GSM_TOTAL>>>(
            p_hhi, p_hlo, whi_2, wlo_2, b2, p_tmp, nullptr, nullptr, DV, DFF);
        // residual + LN2 -> fp32 + hi/lo (next layer's GEMM input)
        ln_kernel<<<MM, 128>>>(p_out, p_tmp, ln2_g + (size_t)l * DV, ln2_bp + (size_t)l * DV,
                               p_out, p_ahi, p_alo);
    }

    ln_kernel<<<MM, 128>>>(p_out, (const float*)nullptr, lnf_g, lnf_bp, (float*)d_out,
                           nullptr, nullptr);
}

// round 12
// speedup vs baseline: 2.3192x; 1.0279x over previous
#include <cuda_runtime.h>
#include <cuda_bf16.h>
#include <math.h>
#include <cstdint>

#define NLAYER 6
#define DV     512
#define NH     8
#define HD     64
#define DFF    2048
#define BB     8
#define LL     1024
#define MM     (BB*LL)
#define QKV_STRIDE (3*DV)

// ---------------- scratch ----------------
__device__ float g_out [MM*DV];
__device__ float g_tmp [MM*DV];
__device__ unsigned char g_kpm[MM];

#define W_IN_SZ   (NLAYER*3*DV*DV)
#define W_OUT_SZ  (NLAYER*DV*DV)
#define W_L1_SZ   (NLAYER*DFF*DV)
#define W_L2_SZ   (NLAYER*DV*DFF)
#define W_TOT     (W_IN_SZ+W_OUT_SZ+W_L1_SZ+W_L2_SZ)
#define OFF_IN    0
#define OFF_OUT   (W_IN_SZ)
#define OFF_L1    (W_IN_SZ+W_OUT_SZ)
#define OFF_L2    (W_IN_SZ+W_OUT_SZ+W_L1_SZ)
__device__ __nv_bfloat16 g_whib[W_TOT];
__device__ __nv_bfloat16 g_wlob[W_TOT];
__device__ __nv_bfloat16 g_ahib[MM*DFF];
__device__ __nv_bfloat16 g_alob[MM*DFF];
__device__ __nv_bfloat16 g_hhib[MM*DFF];
__device__ __nv_bfloat16 g_hlob[MM*DFF];
__device__ __nv_bfloat16 g_qkvh[MM*3*DV];
__device__ __nv_bfloat16 g_qkvl[MM*3*DV];

// ---------------- smem / mma helpers ----------------
__device__ __forceinline__ uint32_t s2u(const void* p) {
    uint32_t a;
    asm("{ .reg .u64 t; cvta.to.shared.u64 t, %1; cvt.u32.u64 %0, t; }" : "=r"(a) : "l"(p));
    return a;
}
__device__ __forceinline__ void cpa16(uint32_t dst, const void* src) {
    asm volatile("cp.async.cg.shared.global [%0], [%1], 16;" :: "r"(dst), "l"(src) : "memory");
}
__device__ __forceinline__ void cpa_commit() { asm volatile("cp.async.commit_group;" ::: "memory"); }
__device__ __forceinline__ void cpa_wait0() { asm volatile("cp.async.wait_group 0;" ::: "memory"); }
__device__ __forceinline__ void cpa_wait1() { asm volatile("cp.async.wait_group 1;" ::: "memory"); }
__device__ __forceinline__ void ldmx4(uint32_t* r, uint32_t addr) {
    asm volatile("ldmatrix.sync.aligned.m8n8.x4.shared.b16 {%0,%1,%2,%3}, [%4];"
        : "=r"(r[0]), "=r"(r[1]), "=r"(r[2]), "=r"(r[3]) : "r"(addr));
}
__device__ __forceinline__ void ldmx4t(uint32_t* r, uint32_t addr) {
    asm volatile("ldmatrix.sync.aligned.m8n8.x4.trans.shared.b16 {%0,%1,%2,%3}, [%4];"
        : "=r"(r[0]), "=r"(r[1]), "=r"(r[2]), "=r"(r[3]) : "r"(addr));
}
__device__ __forceinline__ void mma_bf16(float* d, const uint32_t* a, const uint32_t* b) {
    asm volatile("mma.sync.aligned.m16n8k16.row.col.f32.bf16.bf16.f32 "
        "{%0,%1,%2,%3}, {%4,%5,%6,%7}, {%8,%9}, {%0,%1,%2,%3};"
        : "+f"(d[0]), "+f"(d[1]), "+f"(d[2]), "+f"(d[3])
        : "r"(a[0]), "r"(a[1]), "r"(a[2]), "r"(a[3]), "r"(b[0]), "r"(b[1]));
}

// hi/lo bf16x2 pair from two floats (x0 -> low half)
#define CVTPAIR(dsthi, dstlo, x0, x1) do { \
    uint32_t _hp; asm("cvt.rn.bf16x2.f32 %0, %1, %2;" : "=r"(_hp) : "f"(x1), "f"(x0)); \
    float _h0 = __uint_as_float(_hp << 16); \
    float _h1 = __uint_as_float(_hp & 0xFFFF0000u); \
    uint32_t _lp; asm("cvt.rn.bf16x2.f32 %0, %1, %2;" : "=r"(_lp) : "f"((x1) - _h1), "f"((x0) - _h0)); \
    (dsthi) = _hp; (dstlo) = _lp; } while(0)

// ---------------- key padding mask ----------------
__global__ void kpm_kernel(const float* __restrict__ x, unsigned char* __restrict__ kpm)
{
    int row = blockIdx.x;
    int t = threadIdx.x;
    int nz = 0;
    for (int c = t; c < DV; c += 128)
        nz |= (x[(size_t)row * DV + c] != 0.0f) ? 1 : 0;
    nz = __syncthreads_or(nz);
    if (t == 0) kpm[row] = nz ? 0 : 1;
}

// ---------------- copy + hi/lo split (initial x) ----------------
__global__ void copy_split_kernel(const float* __restrict__ src, float* __restrict__ dst,
                                  __nv_bfloat16* __restrict__ hi, __nv_bfloat16* __restrict__ lo, int n4)
{
    int i = blockIdx.x * blockDim.x + threadIdx.x;
    if (i >= n4) return;
    float4 v = ((const float4*)src)[i];
    ((float4*)dst)[i] = v;
    __nv_bfloat16 h0 = __float2bfloat16_rn(v.x), h1 = __float2bfloat16_rn(v.y);
    __nv_bfloat16 h2 = __float2bfloat16_rn(v.z), h3 = __float2bfloat16_rn(v.w);
    __nv_bfloat162* hp = (__nv_bfloat162*)hi;
    __nv_bfloat162* lp = (__nv_bfloat162*)lo;
    hp[2*i]   = __nv_bfloat162(h0, h1);
    hp[2*i+1] = __nv_bfloat162(h2, h3);
    lp[2*i]   = __nv_bfloat162(__float2bfloat16_rn(v.x - __bfloat162float(h0)),
                               __float2bfloat16_rn(v.y - __bfloat162float(h1)));
    lp[2*i+1] = __nv_bfloat162(__float2bfloat16_rn(v.z - __bfloat162float(h2)),
                               __float2bfloat16_rn(v.w - __bfloat162float(h3)));
}

// ---------------- weight hi/lo split ----------------
__global__ void splitb_kernel(const float* __restrict__ src,
                              __nv_bfloat16* __restrict__ hi,
                              __nv_bfloat16* __restrict__ lo, int n4)
{
    int i = blockIdx.x * blockDim.x + threadIdx.x;
    if (i >= n4) return;
    float4 v = ((const float4*)src)[i];
    __nv_bfloat16 h0 = __float2bfloat16_rn(v.x), h1 = __float2bfloat16_rn(v.y);
    __nv_bfloat16 h2 = __float2bfloat16_rn(v.z), h3 = __float2bfloat16_rn(v.w);
    __nv_bfloat162* hp = (__nv_bfloat162*)hi;
    __nv_bfloat162* lp = (__nv_bfloat162*)lo;
    hp[2*i]   = __nv_bfloat162(h0, h1);
    hp[2*i+1] = __nv_bfloat162(h2, h3);
    lp[2*i]   = __nv_bfloat162(__float2bfloat16_rn(v.x - __bfloat162float(h0)),
                               __float2bfloat16_rn(v.y - __bfloat162float(h1)));
    lp[2*i+1] = __nv_bfloat162(__float2bfloat16_rn(v.z - __bfloat162float(h2)),
                               __float2bfloat16_rn(v.w - __bfloat162float(h3)));
}

// ---------------- HMMA bf16 hi/lo GEMM (3-stage cp.async, 1 barrier/chunk) ----------------
#define GSM_STAGE 32768
#define GSM_TOTAL (3*GSM_STAGE)

__device__ __forceinline__ uint32_t swz(int row, int kch) {
    return (uint32_t)(row * 64 + (((kch + ((row >> 1) & 3)) & 3) << 4));
}

template<bool GELU, bool SPLIT>
__global__ __launch_bounds__(256) void hmma_gemm(
    const __nv_bfloat16* __restrict__ Ahi, const __nv_bfloat16* __restrict__ Alo,
    const __nv_bfloat16* __restrict__ Whi, const __nv_bfloat16* __restrict__ Wlo,
    const float* __restrict__ bias, float* __restrict__ C,
    __nv_bfloat16* __restrict__ Chi, __nv_bfloat16* __restrict__ Clo,
    int N, int K)
{
    extern __shared__ __align__(16) char sm[];
    const uint32_t sb = s2u(sm);
    const int t = threadIdx.x;
    const int bm = blockIdx.y * 128, bn = blockIdx.x * 128;
    const int w = t >> 5, l = t & 31;
    const int wm = w & 3, wn = w >> 2;

    float acc[2][8][4];
#pragma unroll
    for (int mt = 0; mt < 2; mt++)
#pragma unroll
        for (int nt = 0; nt < 8; nt++)
#pragma unroll
            for (int e = 0; e < 4; e++) acc[mt][nt][e] = 0.0f;

    const int nch = K >> 5;

    auto load_stage = [&](int stage, int kt) {
        const uint32_t base = sb + stage * GSM_STAGE;
        const int k0 = kt << 5;
#pragma unroll
        for (int q = 0; q < 2; q++) {
            int ch = t + (q << 8);
            int row = ch >> 2, c = ch & 3;
            uint32_t so = swz(row, c);
            size_t ga = (size_t)(bm + row) * K + k0 + c * 8;
            size_t gb = (size_t)(bn + row) * K + k0 + c * 8;
            cpa16(base + so,          Ahi + ga);
            cpa16(base + 8192 + so,   Alo + ga);
            cpa16(base + 16384 + so,  Whi + gb);
            cpa16(base + 24576 + so,  Wlo + gb);
        }
        cpa_commit();
    };

    load_stage(0, 0);
    load_stage(1, 1);   // nch >= 16 always here

    int stg = 0;
    for (int c = 0; c < nch; ++c) {
        if (c + 1 < nch) cpa_wait1(); else cpa_wait0();
        __syncthreads();
        if (c + 2 < nch) {
            int ns = stg + 2; if (ns >= 3) ns -= 3;
            load_stage(ns, c + 2);
        }

        const uint32_t base = sb + stg * GSM_STAGE;
#pragma unroll
        for (int kk = 0; kk < 2; kk++) {
            uint32_t ah[2][4], al[2][4];
#pragma unroll
            for (int mt = 0; mt < 2; mt++) {
                int row = wm * 32 + mt * 16 + (l & 15);
                int kch = kk * 2 + (l >> 4);
                uint32_t off = swz(row, kch);
                ldmx4(ah[mt], base + off);
                ldmx4(al[mt], base + 8192 + off);
            }
            uint32_t bh[8][2], bl[8][2];
#pragma unroll
            for (int nt2 = 0; nt2 < 4; nt2++) {
                int row = wn * 64 + nt2 * 16 + (l & 7) + ((l >> 4) << 3);
                int kch = kk * 2 + ((l >> 3) & 1);
                uint32_t off = swz(row, kch);
                uint32_t r[4];
                ldmx4(r, base + 16384 + off);
                bh[nt2*2][0] = r[0]; bh[nt2*2][1] = r[1];
                bh[nt2*2+1][0] = r[2]; bh[nt2*2+1][1] = r[3];
                ldmx4(r, base + 24576 + off);
                bl[nt2*2][0] = r[0]; bl[nt2*2][1] = r[1];
                bl[nt2*2+1][0] = r[2]; bl[nt2*2+1][1] = r[3];
            }
#pragma unroll
            for (int mt = 0; mt < 2; mt++)
#pragma unroll
                for (int nt = 0; nt < 8; nt++) {
                    mma_bf16(acc[mt][nt], ah[mt], bh[nt]);
                    mma_bf16(acc[mt][nt], ah[mt], bl[nt]);
                    mma_bf16(acc[mt][nt], al[mt], bh[nt]);
                }
        }
        if (++stg >= 3) stg = 0;
    }

#pragma unroll
    for (int mt = 0; mt < 2; mt++) {
        int row = bm + wm * 32 + mt * 16 + (l >> 2);
#pragma unroll
        for (int nt = 0; nt < 8; nt++) {
            int col = bn + wn * 64 + nt * 8 + 2 * (l & 3);
            float b0 = bias[col], b1 = bias[col + 1];
            float v0 = acc[mt][nt][0] + b0;
            float v1 = acc[mt][nt][1] + b1;
            float v2 = acc[mt][nt][2] + b0;
            float v3 = acc[mt][nt][3] + b1;
            if (GELU) {
                v0 = 0.5f * v0 * (1.0f + erff(v0 * 0.70710678118654752f));
                v1 = 0.5f * v1 * (1.0f + erff(v1 * 0.70710678118654752f));
                v2 = 0.5f * v2 * (1.0f + erff(v2 * 0.70710678118654752f));
                v3 = 0.5f * v3 * (1.0f + erff(v3 * 0.70710678118654752f));
            }
            if (SPLIT) {
                uint32_t hp, lp;
                CVTPAIR(hp, lp, v0, v1);
                *(uint32_t*)(Chi + (size_t)row * N + col) = hp;
                *(uint32_t*)(Clo + (size_t)row * N + col) = lp;
                CVTPAIR(hp, lp, v2, v3);
                *(uint32_t*)(Chi + (size_t)(row + 8) * N + col) = hp;
                *(uint32_t*)(Clo + (size_t)(row + 8) * N + col) = lp;
            } else {
                *(float2*)(C + (size_t)row * N + col)       = make_float2(v0, v1);
                *(float2*)(C + (size_t)(row + 8) * N + col) = make_float2(v2, v3);
            }
        }
    }
}

// ---------------- mma.sync flash attention (3-stage K/V pipeline) ----------------
// smem: stages 0/1/2 at 0/32768/65536 (each: Kh 0, Kl 8192, Vh 16384, Vl 24576);
// sbias @98304 (4KB), smask @102400 (4KB). Q staged in stage0 region first.
#define ASM_TOTAL 106496

__global__ __launch_bounds__(256, 1) void attn_mma(
    const __nv_bfloat16* __restrict__ qkvh, const __nv_bfloat16* __restrict__ qkvl,
    const float* __restrict__ dist_emb, const unsigned char* __restrict__ kpm,
    __nv_bfloat16* __restrict__ ohi, __nv_bfloat16* __restrict__ olo)
{
    extern __shared__ __align__(16) char sm[];
    const uint32_t sb0 = s2u(sm);
    const int bh = blockIdx.x;
    const int b = bh >> 3, h = bh & 7;
    const int qbi = (int)gridDim.y - 1 - (int)blockIdx.y;   // long blocks first
    const int qbase = qbi * 128;
    const int t = threadIdx.x;
    const int w = t >> 5, l = t & 31;

    float* sbias = (float*)(sm + 98304);
    float* smask = (float*)(sm + 102400);
    for (int d = t; d < LL; d += 256) {
        sbias[d] = dist_emb[d * NH + h];
        smask[d] = kpm[b * LL + d] ? -2e30f : 0.0f;
    }

    // stage Q (hi @ sb0, lo @ sb0+16384)
#pragma unroll
    for (int q = 0; q < 4; q++) {
        int c = t + q * 256;
        int row = c >> 3, ch = c & 7;
        size_t g = (size_t)(b * LL + qbase + row) * QKV_STRIDE + h * HD + ch * 8;
        uint32_t off = (uint32_t)(row * 128 + ((ch ^ (row & 7)) << 4));
        cpa16(sb0 + off, qkvh + g);
        cpa16(sb0 + 16384 + off, qkvl + g);
    }
    cpa_commit();
    cpa_wait0();
    __syncthreads();

    uint32_t qh[4][4], ql[4][4];
    {
        int qrow = w * 16 + (l & 15);
#pragma unroll
        for (int j = 0; j < 4; j++) {
            int ch = 2 * j + (l >> 4);
            uint32_t addr = sb0 + qrow * 128 + ((ch ^ (qrow & 7)) << 4);
            ldmx4(qh[j], addr);
            ldmx4(ql[j], addr + 16384);
        }
    }
    __syncthreads();   // Q extracted before stage0 K/V overwrite

    float o[8][4];
#pragma unroll
    for (int dt = 0; dt < 8; dt++)
#pragma unroll
        for (int e = 0; e < 4; e++) o[dt][e] = 0.0f;
    float m0 = -1e30f, m1 = -1e30f, ls0 = 0.0f, ls1 = 0.0f;
    const int i0 = qbase + w * 16 + (l >> 2);
    const int i1 = i0 + 8;
    const int ntile = (qbase + 128) >> 6;

    auto load_kv = [&](int stage, int jt) {
        const uint32_t base = sb0 + stage * 32768;
#pragma unroll
        for (int q = 0; q < 2; q++) {
            int c = t + q * 256;
            int row = c >> 3, ch = c & 7;
            size_t gk = (size_t)(b * LL + jt + row) * QKV_STRIDE + DV + h * HD + ch * 8;
            size_t gv = gk + DV;
            uint32_t off = (uint32_t)(row * 128 + ((ch ^ (row & 7)) << 4));
            cpa16(base + off,          qkvh + gk);
            cpa16(base + 8192 + off,   qkvl + gk);
            cpa16(base + 16384 + off,  qkvh + gv);
            cpa16(base + 24576 + off,  qkvl + gv);
        }
        cpa_commit();
    };

    load_kv(0, 0);
    if (ntile > 1) load_kv(1, 64);

    int stg = 0;
    for (int ti = 0; ti < ntile; ti++) {
        if (ti + 1 < ntile) cpa_wait1(); else cpa_wait0();
        __syncthreads();
        if (ti + 2 < ntile) {
            int ns = stg + 2; if (ns >= 3) ns -= 3;
            load_kv(ns, (ti + 2) << 6);
        }

        const int jt = ti << 6;
        if (jt <= qbase + w * 16 + 15) {
            const uint32_t kb = sb0 + stg * 32768;

            // ---- S = Q K^T (3-term hi/lo) ----
            float s[8][4];
#pragma unroll
            for (int nt = 0; nt < 8; nt++)
#pragma unroll
                for (int e = 0; e < 4; e++) s[nt][e] = 0.0f;

            const int krow = (l & 7) + ((l >> 4) << 3);
#pragma unroll
            for (int kc = 0; kc < 4; kc++) {
                const int kch = 2 * kc + ((l >> 3) & 1);
#pragma unroll
                for (int nt2 = 0; nt2 < 4; nt2++) {
                    int row = nt2 * 16 + krow;
                    uint32_t addr = kb + row * 128 + ((kch ^ (row & 7)) << 4);
                    uint32_t rh[4], rl[4];
                    ldmx4(rh, addr);
                    ldmx4(rl, addr + 8192);
                    uint32_t b0h[2] = {rh[0], rh[1]}, b1h[2] = {rh[2], rh[3]};
                    uint32_t b0l[2] = {rl[0], rl[1]}, b1l[2] = {rl[2], rl[3]};
                    mma_bf16(s[nt2*2],   qh[kc], b0h);
                    mma_bf16(s[nt2*2],   qh[kc], b0l);
                    mma_bf16(s[nt2*2],   ql[kc], b0h);
                    mma_bf16(s[nt2*2+1], qh[kc], b1h);
                    mma_bf16(s[nt2*2+1], qh[kc], b1l);
                    mma_bf16(s[nt2*2+1], ql[kc], b1h);
                }
            }

            // ---- scale + bias + causal/kpm mask ----
            const float scale = 0.125f;
            const int jc = jt + 2 * (l & 3);
#pragma unroll
            for (int nt = 0; nt < 8; nt++) {
                int j0 = jc + nt * 8;
                float mk0 = smask[j0], mk1 = smask[j0 + 1];
                int d0 = i0 - j0;
                int d1 = i1 - j0;
                s[nt][0] = (d0 >= 0)     ? fmaf(s[nt][0], scale, sbias[d0]     + mk0) : -1e30f;
                s[nt][1] = (d0 >= 1)     ? fmaf(s[nt][1], scale, sbias[d0 - 1] + mk1) : -1e30f;
                s[nt][2] = (d1 >= 0)     ? fmaf(s[nt][2], scale, sbias[d1]     + mk0) : -1e30f;
                s[nt][3] = (d1 >= 1)     ? fmaf(s[nt][3], scale, sbias[d1 - 1] + mk1) : -1e30f;
            }

            // ---- online softmax ----
            float mx0 = -1e30f, mx1 = -1e30f;
#pragma unroll
            for (int nt = 0; nt < 8; nt++) {
                mx0 = fmaxf(mx0, fmaxf(s[nt][0], s[nt][1]));
                mx1 = fmaxf(mx1, fmaxf(s[nt][2], s[nt][3]));
            }
            mx0 = fmaxf(mx0, __shfl_xor_sync(0xFFFFFFFFu, mx0, 1));
            mx0 = fmaxf(mx0, __shfl_xor_sync(0xFFFFFFFFu, mx0, 2));
            mx1 = fmaxf(mx1, __shfl_xor_sync(0xFFFFFFFFu, mx1, 1));
            mx1 = fmaxf(mx1, __shfl_xor_sync(0xFFFFFFFFu, mx1, 2));
            float mn0 = fmaxf(m0, mx0), mn1 = fmaxf(m1, mx1);
            float a0 = __expf(m0 - mn0), a1 = __expf(m1 - mn1);
            m0 = mn0; m1 = mn1;
            ls0 *= a0; ls1 *= a1;
#pragma unroll
            for (int dt = 0; dt < 8; dt++) {
                o[dt][0] *= a0; o[dt][1] *= a0;
                o[dt][2] *= a1; o[dt][3] *= a1;
            }
#pragma unroll
            for (int nt = 0; nt < 8; nt++) {
                s[nt][0] = __expf(s[nt][0] - mn0);
                s[nt][1] = __expf(s[nt][1] - mn0);
                s[nt][2] = __expf(s[nt][2] - mn1);
                s[nt][3] = __expf(s[nt][3] - mn1);
                ls0 += s[nt][0] + s[nt][1];
                ls1 += s[nt][2] + s[nt][3];
            }

            // ---- P -> bf16 hi/lo A-fragments ----
            uint32_t ph[4][4], pl[4][4];
#pragma unroll
            for (int j = 0; j < 4; j++) {
                CVTPAIR(ph[j][0], pl[j][0], s[2*j][0],   s[2*j][1]);
                CVTPAIR(ph[j][1], pl[j][1], s[2*j][2],   s[2*j][3]);
                CVTPAIR(ph[j][2], pl[j][2], s[2*j+1][0], s[2*j+1][1]);
                CVTPAIR(ph[j][3], pl[j][3], s[2*j+1][2], s[2*j+1][3]);
            }

            // ---- O += P V (3-term) ----
            const int vsub = (l & 7) + (((l >> 3) & 1) << 3);
#pragma unroll
            for (int j = 0; j < 4; j++) {
                int vrow = j * 16 + vsub;
#pragma unroll
                for (int dp = 0; dp < 4; dp++) {
                    int ch = 2 * dp + (l >> 4);
                    uint32_t addr = kb + 16384 + vrow * 128 + ((ch ^ (vrow & 7)) << 4);
                    uint32_t rh[4], rl[4];
                    ldmx4t(rh, addr);
                    ldmx4t(rl, addr + 8192);
                    uint32_t v0h[2] = {rh[0], rh[1]}, v1h[2] = {rh[2], rh[3]};
                    uint32_t v0l[2] = {rl[0], rl[1]}, v1l[2] = {rl[2], rl[3]};
                    mma_bf16(o[2*dp],   ph[j], v0h);
                    mma_bf16(o[2*dp],   pl[j], v0h);
                    mma_bf16(o[2*dp],   ph[j], v0l);
                    mma_bf16(o[2*dp+1], ph[j], v1h);
                    mma_bf16(o[2*dp+1], pl[j], v1h);
                    mma_bf16(o[2*dp+1], ph[j], v1l);
                }
            }
        }
        if (++stg >= 3) stg = 0;
    }

    // ---- finalize ----
    ls0 += __shfl_xor_sync(0xFFFFFFFFu, ls0, 1);
    ls0 += __shfl_xor_sync(0xFFFFFFFFu, ls0, 2);
    ls1 += __shfl_xor_sync(0xFFFFFFFFu, ls1, 1);
    ls1 += __shfl_xor_sync(0xFFFFFFFFu, ls1, 2);
    float inv0 = 1.0f / ls0, inv1 = 1.0f / ls1;

#pragma unroll
    for (int dt = 0; dt < 8; dt++) {
        int col = h * HD + dt * 8 + 2 * (l & 3);
        size_t r0 = (size_t)(b * LL + i0) * DV + col;
        size_t r1 = (size_t)(b * LL + i1) * DV + col;
        uint32_t hp, lp;
        CVTPAIR(hp, lp, o[dt][0] * inv0, o[dt][1] * inv0);
        *(uint32_t*)(ohi + r0) = hp;
        *(uint32_t*)(olo + r0) = lp;
        CVTPAIR(hp, lp, o[dt][2] * inv1, o[dt][3] * inv1);
        *(uint32_t*)(ohi + r1) = hp;
        *(uint32_t*)(olo + r1) = lp;
    }
}

// ---------------- residual + LayerNorm (+ optional bf16 hi/lo out) ----------------
__global__ __launch_bounds__(128) void ln_kernel(
    const float* __restrict__ x, const float* __restrict__ res,
    const float* __restrict__ g, const float* __restrict__ beta,
    float* __restrict__ outp,
    __nv_bfloat16* __restrict__ ohi, __nv_bfloat16* __restrict__ olo)
{
    const int row = blockIdx.x;
    const int t = threadIdx.x;
    const float* xr = x + (size_t)row * DV;

    float v[4];
#pragma unroll
    for (int k = 0; k < 4; k++) {
        int c = k * 128 + t;
        float val = xr[c];
        if (res) val += res[(size_t)row * DV + c];
        v[k] = val;
    }
    float s = 0.0f, ss = 0.0f;
#pragma unroll
    for (int k = 0; k < 4; k++) { s += v[k]; ss += v[k] * v[k]; }
#pragma unroll
    for (int o = 16; o > 0; o >>= 1) {
        s  += __shfl_xor_sync(0xFFFFFFFFu, s,  o);
        ss += __shfl_xor_sync(0xFFFFFFFFu, ss, o);
    }
    __shared__ float rs[4], rss[4];
    int w = t >> 5;
    if ((t & 31) == 0) { rs[w] = s; rss[w] = ss; }
    __syncthreads();
    s  = rs[0] + rs[1] + rs[2] + rs[3];
    ss = rss[0] + rss[1] + rss[2] + rss[3];
    float mean = s * (1.0f / DV);
    float var  = ss * (1.0f / DV) - mean * mean;
    float r = rsqrtf(var + 1e-5f);
#pragma unroll
    for (int k = 0; k < 4; k++) {
        int c = k * 128 + t;
        float val = (v[k] - mean) * r * g[c] + beta[c];
        outp[(size_t)row * DV + c] = val;
        if (ohi) {
            __nv_bfloat16 hh = __float2bfloat16_rn(val);
            ohi[(size_t)row * DV + c] = hh;
            olo[(size_t)row * DV + c] = __float2bfloat16_rn(val - __bfloat162float(hh));
        }
    }
}

// ---------------- host launcher ----------------
extern "C" void kernel_launch(void* const* d_in, const int* in_sizes, int n_in,
                              void* d_out, int out_size)
{
    (void)in_sizes; (void)n_in; (void)out_size;
    const float* x         = (const float*)d_in[0];
    const float* dist_emb  = (const float*)d_in[1];
    const float* in_proj_w = (const float*)d_in[2];
    const float* in_proj_b = (const float*)d_in[3];
    const float* out_w     = (const float*)d_in[4];
    const float* out_b     = (const float*)d_in[5];
    const float* lin1_w    = (const float*)d_in[6];
    const float* lin1_b    = (const float*)d_in[7];
    const float* lin2_w    = (const float*)d_in[8];
    const float* lin2_b    = (const float*)d_in[9];
    const float* ln1_g     = (const float*)d_in[10];
    const float* ln1_bp    = (const float*)d_in[11];
    const float* ln2_g     = (const float*)d_in[12];
    const float* ln2_bp    = (const float*)d_in[13];
    const float* lnf_g     = (const float*)d_in[14];
    const float* lnf_bp    = (const float*)d_in[15];

    float *p_out, *p_tmp;
    __nv_bfloat16 *p_whi, *p_wlo, *p_ahi, *p_alo, *p_hhi, *p_hlo, *p_qkvh, *p_qkvl;
    unsigned char* p_kpm;
    cudaGetSymbolAddress((void**)&p_out,  g_out);
    cudaGetSymbolAddress((void**)&p_tmp,  g_tmp);
    cudaGetSymbolAddress((void**)&p_whi,  g_whib);
    cudaGetSymbolAddress((void**)&p_wlo,  g_wlob);
    cudaGetSymbolAddress((void**)&p_ahi,  g_ahib);
    cudaGetSymbolAddress((void**)&p_alo,  g_alob);
    cudaGetSymbolAddress((void**)&p_hhi,  g_hhib);
    cudaGetSymbolAddress((void**)&p_hlo,  g_hlob);
    cudaGetSymbolAddress((void**)&p_qkvh, g_qkvh);
    cudaGetSymbolAddress((void**)&p_qkvl, g_qkvl);
    cudaGetSymbolAddress((void**)&p_kpm,  g_kpm);

    cudaFuncSetAttribute(hmma_gemm<false,false>, cudaFuncAttributeMaxDynamicSharedMemorySize, GSM_TOTAL);
    cudaFuncSetAttribute(hmma_gemm<false,true>,  cudaFuncAttributeMaxDynamicSharedMemorySize, GSM_TOTAL);
    cudaFuncSetAttribute(hmma_gemm<true,true>,   cudaFuncAttributeMaxDynamicSharedMemorySize, GSM_TOTAL);
    cudaFuncSetAttribute(attn_mma, cudaFuncAttributeMaxDynamicSharedMemorySize, ASM_TOTAL);

    kpm_kernel<<<MM, 128>>>(x, p_kpm);
    {
        int n4 = MM * DV / 4;
        copy_split_kernel<<<(n4 + 255) / 256, 256>>>(x, p_out, p_ahi, p_alo, n4);
    }

    // split weights once
    {
        int n4;
        n4 = W_IN_SZ  / 4; splitb_kernel<<<(n4 + 255) / 256, 256>>>(in_proj_w, p_whi + OFF_IN,  p_wlo + OFF_IN,  n4);
        n4 = W_OUT_SZ / 4; splitb_kernel<<<(n4 + 255) / 256, 256>>>(out_w,     p_whi + OFF_OUT, p_wlo + OFF_OUT, n4);
        n4 = W_L1_SZ  / 4; splitb_kernel<<<(n4 + 255) / 256, 256>>>(lin1_w,    p_whi + OFF_L1,  p_wlo + OFF_L1,  n4);
        n4 = W_L2_SZ  / 4; splitb_kernel<<<(n4 + 255) / 256, 256>>>(lin2_w,    p_whi + OFF_L2,  p_wlo + OFF_L2,  n4);
    }

    for (int l = 0; l < NLAYER; l++) {
        const __nv_bfloat16* whi_in = p_whi + OFF_IN  + (size_t)l * 3 * DV * DV;
        const __nv_bfloat16* wlo_in = p_wlo + OFF_IN  + (size_t)l * 3 * DV * DV;
        const __nv_bfloat16* whi_o  = p_whi + OFF_OUT + (size_t)l * DV * DV;
        const __nv_bfloat16* wlo_o  = p_wlo + OFF_OUT + (size_t)l * DV * DV;
        const __nv_bfloat16* whi_1  = p_whi + OFF_L1  + (size_t)l * DFF * DV;
        const __nv_bfloat16* wlo_1  = p_wlo + OFF_L1  + (size_t)l * DFF * DV;
        const __nv_bfloat16* whi_2  = p_whi + OFF_L2  + (size_t)l * DV * DFF;
        const __nv_bfloat16* wlo_2  = p_wlo + OFF_L2  + (size_t)l * DV * DFF;
        const float* bq  = in_proj_b + (size_t)l * 3 * DV;
        const float* bo  = out_b     + (size_t)l * DV;
        const float* b1  = lin1_b    + (size_t)l * DFF;
        const float* b2  = lin2_b    + (size_t)l * DV;

        // QKV projection -> bf16 hi/lo qkv
        hmma_gemm<false,true><<<dim3(3 * DV / 128, MM / 128), 256, GSM_TOTAL>>>(
            p_ahi, p_alo, whi_in, wlo_in, bq, nullptr, p_qkvh, p_qkvl, 3 * DV, DV);
        // mma flash attention -> attn activation as hi/lo bf16
        attn_mma<<<dim3(BB * NH, LL / 128), 256, ASM_TOTAL>>>(
            p_qkvh, p_qkvl, dist_emb, p_kpm, p_ahi, p_alo);
        // output projection
        hmma_gemm<false,false><<<dim3(DV / 128, MM / 128), 256, GSM_TOTAL>>>(
            p_ahi, p_alo, whi_o, wlo_o, bo, p_tmp, nullptr, nullptr, DV, DV);
        // residual + LN1 -> fp32 + hi/lo
        ln_kernel<<<MM, 128>>>(p_out, p_tmp, ln1_g + (size_t)l * DV, ln1_bp + (size_t)l * DV,
                               p_out, p_ahi, p_alo);
        // FFN up: gelu epilogue writes hi/lo directly
        hmma_gemm<true,true><<<dim3(DFF / 128, MM / 128), 256, GSM_TOTAL>>>(
            p_ahi, p_alo, whi_1, wlo_1, b1, nullptr, p_hhi, p_hlo, DFF, DV);
        // FFN down
        hmma_gemm<false,false><<<dim3(DV / 128, MM / 128), 256, GSM_TOTAL>>>(
            p_hhi, p_hlo, whi_2, wlo_2, b2, p_tmp, nullptr, nullptr, DV, DFF);
        // residual + LN2 -> fp32 + hi/lo (next layer's GEMM input)
        ln_kernel<<<MM, 128>>>(p_out, p_tmp, ln2_g + (size_t)l * DV, ln2_bp + (size_t)l * DV,
                               p_out, p_ahi, p_alo);
    }

    ln_kernel<<<MM, 128>>>(p_out, (const float*)nullptr, lnf_g, lnf_bp, (float*)d_out,
                           nullptr, nullptr);
}